// round 2
// baseline (speedup 1.0000x reference)
#include <cuda_runtime.h>

#define NTS  4096
#define SEQL 168
#define HOR  24
#define TT   192
#define FIN  32

// ---- shared layout (floats) -------------------------------------------------
#define OFF_WX  0              // 3*64*32  layer0 x-part weights (i,g,o)
#define OFF_W1  6144           // 3*64*64  layer1 weights (i,g,o)
#define OFF_V   18432          // 192      rank-1 vector: Wy @ W_embed
#define OFF_C0  18624          // 192      b_ih0+b_hh0 + Wy@b_embed
#define OFF_C1  18816          // 192      b_ih1+b_hh1
#define OFF_WMU 19008          // 64
#define OFF_WSG 19072          // 64
#define SM_FLOATS 19136
#define SM_BYTES  (SM_FLOATS * 4)

// Gx kernel shared layout
#define OFFG_WX 0
#define OFFG_C0 6144
#define SMG_BYTES ((6144 + 192) * 4)

// ---- device scratch (static globals: no allocation APIs) --------------------
__device__ float g_Gx[HOR * 192 * NTS];   // [t'][j][n], j in 0..191 (i,g,o)
__device__ float g_carry[NTS];
__device__ float g_mu_fb[NTS * TT];       // fallbacks if out layout differs
__device__ float g_sg_fb[NTS * TT];

__device__ __forceinline__ int rowsel(int g, int u) {
    // gate order in torch W_ih rows: i=[0,64) f=[64,128) g=[128,192) o=[192,256)
    return (g == 0) ? u : ((g == 1) ? 128 + u : 192 + u);
}

__device__ __forceinline__ float fsig(float x) {
    return __fdividef(1.f, 1.f + __expf(-x));
}
__device__ __forceinline__ float ftanh_(float x) {
    // 1 - 2/(exp(2x)+1); exp overflow -> +1, underflow -> -1 (both correct)
    return 1.f - __fdividef(2.f, __expf(2.f * x) + 1.f);
}
__device__ __forceinline__ float fsoftplus(float x) {
    return (x > 15.f) ? x : __logf(1.f + __expf(x));
}

// ---- full weight stage into shared ------------------------------------------
__device__ __forceinline__ void load_full(
    float* sm,
    const float* __restrict__ W_ih, const float* __restrict__ b_ih,
    const float* __restrict__ b_hh, const float* __restrict__ W_embed,
    const float* __restrict__ b_embed, const float* __restrict__ W_mu,
    const float* __restrict__ W_sigma, int tid, int nt)
{
    for (int i = tid; i < 3 * 64 * 32; i += nt) {
        int g = i >> 11, r = i & 2047, u = r >> 5, k = r & 31;
        sm[OFF_WX + i] = W_ih[rowsel(g, u) * 64 + k];
    }
    for (int i = tid; i < 3 * 64 * 64; i += nt) {
        int g = i >> 12, r = i & 4095, u = r >> 6, k = r & 63;
        sm[OFF_W1 + i] = W_ih[16384 + rowsel(g, u) * 64 + k];
    }
    for (int j = tid; j < 192; j += nt) {
        int g = j >> 6, u = j & 63;
        int row = rowsel(g, u);
        float v = 0.f, cb = 0.f;
        #pragma unroll
        for (int e = 0; e < 32; e++) {
            float w = W_ih[row * 64 + 32 + e];
            v  = fmaf(w, W_embed[e], v);
            cb = fmaf(w, b_embed[e], cb);
        }
        sm[OFF_V + j]  = v;
        sm[OFF_C0 + j] = b_ih[row] + b_hh[row] + cb;
        sm[OFF_C1 + j] = b_ih[256 + row] + b_hh[256 + row];
    }
    for (int k = tid; k < 64; k += nt) {
        sm[OFF_WMU + k] = W_mu[k];
        sm[OFF_WSG + k] = W_sigma[k];
    }
}

// ---- layer1 + head, h1 fully in registers -----------------------------------
__device__ __forceinline__ void layer1_head(const float* sm, const float h1[64],
                                            float& mu, float& sg)
{
    #pragma unroll
    for (int u = 0; u < 64; u++) {
        float ai = sm[OFF_C1 + u];
        float ag = sm[OFF_C1 + 64 + u];
        float ao = sm[OFF_C1 + 128 + u];
        const float4* wi = (const float4*)&sm[OFF_W1 + u * 64];
        const float4* wg = (const float4*)&sm[OFF_W1 + 4096 + u * 64];
        const float4* wo = (const float4*)&sm[OFF_W1 + 8192 + u * 64];
        #pragma unroll
        for (int k4 = 0; k4 < 16; k4++) {
            float4 a = wi[k4], b = wg[k4], c = wo[k4];
            float h0v = h1[k4 * 4], h1v = h1[k4 * 4 + 1];
            float h2v = h1[k4 * 4 + 2], h3v = h1[k4 * 4 + 3];
            ai = fmaf(h0v, a.x, ai); ai = fmaf(h1v, a.y, ai);
            ai = fmaf(h2v, a.z, ai); ai = fmaf(h3v, a.w, ai);
            ag = fmaf(h0v, b.x, ag); ag = fmaf(h1v, b.y, ag);
            ag = fmaf(h2v, b.z, ag); ag = fmaf(h3v, b.w, ag);
            ao = fmaf(h0v, c.x, ao); ao = fmaf(h1v, c.y, ao);
            ao = fmaf(h2v, c.z, ao); ao = fmaf(h3v, c.w, ao);
        }
        float cc = fsig(ai) * ftanh_(ag);
        float h2 = fsig(ao) * ftanh_(cc);
        float r  = fmaxf(h2, 0.f);
        mu = fmaf(r, sm[OFF_WMU + u], mu);
        sg = fmaf(r, sm[OFF_WSG + u], sg);
    }
}

// ---- kernel A: parallel teacher-forced steps, t in [0, 168) ------------------
__global__ void __launch_bounds__(256) kA(
    const float* __restrict__ X, const float* __restrict__ y,
    const float* __restrict__ W_ih, const float* __restrict__ b_ih,
    const float* __restrict__ b_hh, const float* __restrict__ W_embed,
    const float* __restrict__ b_embed, const float* __restrict__ W_mu,
    const float* __restrict__ b_mu, const float* __restrict__ W_sigma,
    const float* __restrict__ b_sigma,
    float* __restrict__ out_yp, float* __restrict__ out_mu,
    float* __restrict__ out_sg)
{
    extern __shared__ float sm[];
    load_full(sm, W_ih, b_ih, b_hh, W_embed, b_embed, W_mu, W_sigma,
              threadIdx.x, 256);
    __syncthreads();

    int n = blockIdx.x * 256 + threadIdx.x;
    int t = blockIdx.y;

    float x[32];
    const float4* xp = (const float4*)(X + (n * SEQL + t) * FIN);
    #pragma unroll
    for (int k4 = 0; k4 < 8; k4++) {
        float4 v = xp[k4];
        x[k4 * 4] = v.x; x[k4 * 4 + 1] = v.y;
        x[k4 * 4 + 2] = v.z; x[k4 * 4 + 3] = v.w;
    }
    float yn = y[n * SEQL + t];

    float h1[64];
    #pragma unroll
    for (int u = 0; u < 64; u++) {
        float ai = fmaf(yn, sm[OFF_V + u],        sm[OFF_C0 + u]);
        float ag = fmaf(yn, sm[OFF_V + 64 + u],   sm[OFF_C0 + 64 + u]);
        float ao = fmaf(yn, sm[OFF_V + 128 + u],  sm[OFF_C0 + 128 + u]);
        const float4* wi = (const float4*)&sm[OFF_WX + u * 32];
        const float4* wg = (const float4*)&sm[OFF_WX + 2048 + u * 32];
        const float4* wo = (const float4*)&sm[OFF_WX + 4096 + u * 32];
        #pragma unroll
        for (int k4 = 0; k4 < 8; k4++) {
            float4 a = wi[k4], b = wg[k4], c = wo[k4];
            float x0 = x[k4 * 4], x1 = x[k4 * 4 + 1];
            float x2 = x[k4 * 4 + 2], x3 = x[k4 * 4 + 3];
            ai = fmaf(x0, a.x, ai); ai = fmaf(x1, a.y, ai);
            ai = fmaf(x2, a.z, ai); ai = fmaf(x3, a.w, ai);
            ag = fmaf(x0, b.x, ag); ag = fmaf(x1, b.y, ag);
            ag = fmaf(x2, b.z, ag); ag = fmaf(x3, b.w, ag);
            ao = fmaf(x0, c.x, ao); ao = fmaf(x1, c.y, ao);
            ao = fmaf(x2, c.z, ao); ao = fmaf(x3, c.w, ao);
        }
        float cc = fsig(ai) * ftanh_(ag);
        h1[u] = fsig(ao) * ftanh_(cc);
    }

    float mu = b_mu[0], sg = b_sigma[0];
    layer1_head(sm, h1, mu, sg);

    float sigma = fsoftplus(sg) + 1e-6f;
    out_mu[n * TT + t] = mu;
    out_sg[n * TT + t] = sigma;

    if (t == SEQL - 1) {
        float inv = __fdividef(1.f, sigma);
        float d = yn - mu;
        float lik = 0.3989422804014327f * inv * __expf(-0.5f * d * d * inv * inv);
        out_yp[n * HOR] = lik;
        g_carry[n] = lik;
    }
}

// ---- kernel Gx: precompute layer-0 x-part for t in [168, 192) ----------------
__global__ void __launch_bounds__(256) kGx(
    const float* __restrict__ Xf, const float* __restrict__ W_ih,
    const float* __restrict__ b_ih, const float* __restrict__ b_hh,
    const float* __restrict__ b_embed)
{
    extern __shared__ float sm[];
    for (int i = threadIdx.x; i < 3 * 64 * 32; i += 256) {
        int g = i >> 11, r = i & 2047, u = r >> 5, k = r & 31;
        sm[OFFG_WX + i] = W_ih[rowsel(g, u) * 64 + k];
    }
    for (int j = threadIdx.x; j < 192; j += 256) {
        int g = j >> 6, u = j & 63;
        int row = rowsel(g, u);
        float cb = 0.f;
        #pragma unroll
        for (int e = 0; e < 32; e++)
            cb = fmaf(W_ih[row * 64 + 32 + e], b_embed[e], cb);
        sm[OFFG_C0 + j] = b_ih[row] + b_hh[row] + cb;
    }
    __syncthreads();

    int n  = blockIdx.x * 256 + threadIdx.x;
    int tp = blockIdx.y;

    float x[32];
    const float4* xp = (const float4*)(Xf + (n * HOR + tp) * FIN);
    #pragma unroll
    for (int k4 = 0; k4 < 8; k4++) {
        float4 v = xp[k4];
        x[k4 * 4] = v.x; x[k4 * 4 + 1] = v.y;
        x[k4 * 4 + 2] = v.z; x[k4 * 4 + 3] = v.w;
    }

    float* gx = g_Gx + tp * 192 * NTS + n;
    #pragma unroll 4
    for (int u = 0; u < 64; u++) {
        float ai = sm[OFFG_C0 + u];
        float ag = sm[OFFG_C0 + 64 + u];
        float ao = sm[OFFG_C0 + 128 + u];
        const float4* wi = (const float4*)&sm[OFFG_WX + u * 32];
        const float4* wg = (const float4*)&sm[OFFG_WX + 2048 + u * 32];
        const float4* wo = (const float4*)&sm[OFFG_WX + 4096 + u * 32];
        #pragma unroll
        for (int k4 = 0; k4 < 8; k4++) {
            float4 a = wi[k4], b = wg[k4], c = wo[k4];
            float x0 = x[k4 * 4], x1 = x[k4 * 4 + 1];
            float x2 = x[k4 * 4 + 2], x3 = x[k4 * 4 + 3];
            ai = fmaf(x0, a.x, ai); ai = fmaf(x1, a.y, ai);
            ai = fmaf(x2, a.z, ai); ai = fmaf(x3, a.w, ai);
            ag = fmaf(x0, b.x, ag); ag = fmaf(x1, b.y, ag);
            ag = fmaf(x2, b.z, ag); ag = fmaf(x3, b.w, ag);
            ao = fmaf(x0, c.x, ao); ao = fmaf(x1, c.y, ao);
            ao = fmaf(x2, c.z, ao); ao = fmaf(x3, c.w, ao);
        }
        gx[u * NTS] = ai;
        gx[(64 + u) * NTS] = ag;
        gx[(128 + u) * NTS] = ao;
    }
}

// ---- kernel B: 24-step recurrence, lane = series -----------------------------
__global__ void __launch_bounds__(32) kB(
    const float* __restrict__ W_ih, const float* __restrict__ b_ih,
    const float* __restrict__ b_hh, const float* __restrict__ W_embed,
    const float* __restrict__ b_embed, const float* __restrict__ W_mu,
    const float* __restrict__ b_mu, const float* __restrict__ W_sigma,
    const float* __restrict__ b_sigma,
    float* __restrict__ out_yp, float* __restrict__ out_mu,
    float* __restrict__ out_sg)
{
    extern __shared__ float sm[];
    load_full(sm, W_ih, b_ih, b_hh, W_embed, b_embed, W_mu, W_sigma,
              threadIdx.x, 32);
    __syncthreads();

    int n = blockIdx.x * 32 + threadIdx.x;
    float yn = g_carry[n];
    float bmu = b_mu[0], bsg = b_sigma[0];

    #pragma unroll 1
    for (int t = SEQL; t < TT; t++) {
        int tp = t - SEQL;
        const float* gx = g_Gx + tp * 192 * NTS + n;

        float h1[64];
        #pragma unroll
        for (int u = 0; u < 64; u++) {
            float ai = fmaf(yn, sm[OFF_V + u],       gx[u * NTS]);
            float ag = fmaf(yn, sm[OFF_V + 64 + u],  gx[(64 + u) * NTS]);
            float ao = fmaf(yn, sm[OFF_V + 128 + u], gx[(128 + u) * NTS]);
            float cc = fsig(ai) * ftanh_(ag);
            h1[u] = fsig(ao) * ftanh_(cc);
        }

        float mu = bmu, sg = bsg;
        layer1_head(sm, h1, mu, sg);

        float sigma = fsoftplus(sg) + 1e-6f;
        out_mu[n * TT + t] = mu;
        out_sg[n * TT + t] = sigma;

        float inv = __fdividef(1.f, sigma);
        float d = yn - mu;
        float lik = 0.3989422804014327f * inv * __expf(-0.5f * d * d * inv * inv);
        if (t < TT - 1) out_yp[n * HOR + (t - SEQL + 1)] = lik;
        yn = lik;
    }
}

// ---- host launch -------------------------------------------------------------
extern "C" void kernel_launch(void* const* d_in, const int* in_sizes, int n_in,
                              void* d_out, int out_size)
{
    (void)in_sizes; (void)n_in;
    const float* X       = (const float*)d_in[0];
    const float* y       = (const float*)d_in[1];
    const float* Xf      = (const float*)d_in[2];
    const float* W_embed = (const float*)d_in[3];
    const float* b_embed = (const float*)d_in[4];
    const float* W_ih    = (const float*)d_in[5];
    const float* b_ih    = (const float*)d_in[6];
    const float* b_hh    = (const float*)d_in[7];
    const float* W_mu    = (const float*)d_in[8];
    const float* b_mu    = (const float*)d_in[9];
    const float* W_sigma = (const float*)d_in[10];
    const float* b_sigma = (const float*)d_in[11];

    float* out = (float*)d_out;
    float* yp = out;
    float* omu;
    float* osg;
    const int full = NTS * HOR + 2 * NTS * TT;
    if (out_size >= full) {
        omu = out + NTS * HOR;
        osg = omu + NTS * TT;
    } else {
        void* p0; void* p1;
        cudaGetSymbolAddress(&p0, g_mu_fb);
        cudaGetSymbolAddress(&p1, g_sg_fb);
        omu = (float*)p0; osg = (float*)p1;
    }

    cudaFuncSetAttribute(kA, cudaFuncAttributeMaxDynamicSharedMemorySize, SM_BYTES);
    cudaFuncSetAttribute(kB, cudaFuncAttributeMaxDynamicSharedMemorySize, SM_BYTES);

    dim3 gA(NTS / 256, SEQL);
    kA<<<gA, 256, SM_BYTES>>>(X, y, W_ih, b_ih, b_hh, W_embed, b_embed,
                              W_mu, b_mu, W_sigma, b_sigma, yp, omu, osg);

    dim3 gG(NTS / 256, HOR);
    kGx<<<gG, 256, SMG_BYTES>>>(Xf, W_ih, b_ih, b_hh, b_embed);

    kB<<<NTS / 32, 32, SM_BYTES>>>(W_ih, b_ih, b_hh, W_embed, b_embed,
                                   W_mu, b_mu, W_sigma, b_sigma, yp, omu, osg);
}

// round 3
// speedup vs baseline: 2.3663x; 2.3663x over previous
#include <cuda_runtime.h>

#define NTS  4096
#define SEQL 168
#define HOR  24
#define TT   192
#define TR   (NTS*SEQL)   // 688128 teacher rows
#define FR   (NTS*HOR)    // 98304 forecast rows

// ---- device scratch ----------------------------------------------------------
__device__ float g_h1[(size_t)TR * 64];      // [row][u]
__device__ float g_Gx[(size_t)HOR * 192 * NTS]; // [tp][j][n]
__device__ float g_carry[NTS];
__device__ float g_mu_fb[NTS * TT];
__device__ float g_sg_fb[NTS * TT];

__device__ __forceinline__ int rowsel(int g, int u) {
    // torch gate rows: i=[0,64) f=[64,128) g=[128,192) o=[192,256); f skipped
    return (g == 0) ? u : ((g == 1) ? 128 + u : 192 + u);
}
__device__ __forceinline__ float tanhapx(float x) {
    float r; asm("tanh.approx.f32 %0, %1;" : "=f"(r) : "f"(x)); return r;
}
__device__ __forceinline__ float sigapx(float x) {
    return fmaf(0.5f, tanhapx(0.5f * x), 0.5f);
}
__device__ __forceinline__ float fsoftplus(float x) {
    return (x > 15.f) ? x : __logf(1.f + __expf(x));
}

// =============================================================================
// P1a / P1b shared layout (floats)
#define SMA_W   0        // 32*193
#define SMA_X   6176     // 32*132
#define SMA_Y   10400    // 128
#define SMA_V   10528    // 192
#define SMA_C0  10720    // 192
#define SMA_FLOATS 10912
#define SMA_BYTES (SMA_FLOATS * 4)

#define GATE_FMA24(wi, wg, wo, xa, xb)                                  \
    ai[0]=fmaf(wi,xa.x,ai[0]); ai[1]=fmaf(wi,xa.y,ai[1]);               \
    ai[2]=fmaf(wi,xa.z,ai[2]); ai[3]=fmaf(wi,xa.w,ai[3]);               \
    ai[4]=fmaf(wi,xb.x,ai[4]); ai[5]=fmaf(wi,xb.y,ai[5]);               \
    ai[6]=fmaf(wi,xb.z,ai[6]); ai[7]=fmaf(wi,xb.w,ai[7]);               \
    ag[0]=fmaf(wg,xa.x,ag[0]); ag[1]=fmaf(wg,xa.y,ag[1]);               \
    ag[2]=fmaf(wg,xa.z,ag[2]); ag[3]=fmaf(wg,xa.w,ag[3]);               \
    ag[4]=fmaf(wg,xb.x,ag[4]); ag[5]=fmaf(wg,xb.y,ag[5]);               \
    ag[6]=fmaf(wg,xb.z,ag[6]); ag[7]=fmaf(wg,xb.w,ag[7]);               \
    ao[0]=fmaf(wo,xa.x,ao[0]); ao[1]=fmaf(wo,xa.y,ao[1]);               \
    ao[2]=fmaf(wo,xa.z,ao[2]); ao[3]=fmaf(wo,xa.w,ao[3]);               \
    ao[4]=fmaf(wo,xb.x,ao[4]); ao[5]=fmaf(wo,xb.y,ao[5]);               \
    ao[6]=fmaf(wo,xb.z,ao[6]); ao[7]=fmaf(wo,xb.w,ao[7]);

// ---- P1a: layer0 for teacher rows, writes h1 --------------------------------
__global__ void __launch_bounds__(256, 2) kP1a(
    const float* __restrict__ X, const float* __restrict__ y,
    const float* __restrict__ W_ih, const float* __restrict__ b_ih,
    const float* __restrict__ b_hh, const float* __restrict__ W_embed,
    const float* __restrict__ b_embed)
{
    extern __shared__ float sm[];
    int tid = threadIdx.x;
    for (int i = tid; i < 6144; i += 256) {
        int g = i >> 11, u = (i >> 5) & 63, k = i & 31;
        sm[SMA_W + k * 193 + g * 64 + u] = W_ih[rowsel(g, u) * 64 + k];
    }
    for (int j = tid; j < 192; j += 256) {
        int g = j >> 6, u = j & 63, row = rowsel(g, u);
        float v = 0.f, cb = 0.f;
        #pragma unroll
        for (int e = 0; e < 32; e++) {
            float w = W_ih[row * 64 + 32 + e];
            v = fmaf(w, W_embed[e], v); cb = fmaf(w, b_embed[e], cb);
        }
        sm[SMA_V + j] = v;
        sm[SMA_C0 + j] = b_ih[row] + b_hh[row] + cb;
    }
    int rowbase = blockIdx.x * 128;
    const float* xg = X + (size_t)rowbase * 32;
    for (int i = tid; i < 4096; i += 256)
        sm[SMA_X + (i & 31) * 132 + (i >> 5)] = xg[i];
    for (int i = tid; i < 128; i += 256) sm[SMA_Y + i] = y[rowbase + i];
    __syncthreads();

    int u = tid & 63, rg = tid >> 6;
    float vi = sm[SMA_V + u], vg = sm[SMA_V + 64 + u], vo = sm[SMA_V + 128 + u];
    float ci = sm[SMA_C0 + u], cg0 = sm[SMA_C0 + 64 + u], co = sm[SMA_C0 + 128 + u];

    #pragma unroll 1
    for (int rr = 0; rr < 4; rr++) {
        int r0 = rg * 32 + rr * 8;
        float ai[8], ag[8], ao[8];
        #pragma unroll
        for (int i = 0; i < 8; i++) {
            float yn = sm[SMA_Y + r0 + i];
            ai[i] = fmaf(yn, vi, ci);
            ag[i] = fmaf(yn, vg, cg0);
            ao[i] = fmaf(yn, vo, co);
        }
        #pragma unroll 8
        for (int k = 0; k < 32; k++) {
            float wi = sm[SMA_W + k * 193 + u];
            float wg = sm[SMA_W + k * 193 + 64 + u];
            float wo = sm[SMA_W + k * 193 + 128 + u];
            float4 xa = *(const float4*)&sm[SMA_X + k * 132 + r0];
            float4 xb = *(const float4*)&sm[SMA_X + k * 132 + r0 + 4];
            GATE_FMA24(wi, wg, wo, xa, xb)
        }
        #pragma unroll
        for (int i = 0; i < 8; i++) {
            float c = sigapx(ai[i]) * tanhapx(ag[i]);
            float h = sigapx(ao[i]) * tanhapx(c);
            g_h1[(size_t)(rowbase + r0 + i) * 64 + u] = h;
        }
    }
}

// ---- P1b: layer0 x-part for forecast rows, writes Gx ------------------------
__global__ void __launch_bounds__(256, 2) kP1b(
    const float* __restrict__ Xf,
    const float* __restrict__ W_ih, const float* __restrict__ b_ih,
    const float* __restrict__ b_hh, const float* __restrict__ b_embed)
{
    extern __shared__ float sm[];
    int tid = threadIdx.x;
    for (int i = tid; i < 6144; i += 256) {
        int g = i >> 11, u = (i >> 5) & 63, k = i & 31;
        sm[SMA_W + k * 193 + g * 64 + u] = W_ih[rowsel(g, u) * 64 + k];
    }
    for (int j = tid; j < 192; j += 256) {
        int g = j >> 6, u = j & 63, row = rowsel(g, u);
        float cb = 0.f;
        #pragma unroll
        for (int e = 0; e < 32; e++)
            cb = fmaf(W_ih[row * 64 + 32 + e], b_embed[e], cb);
        sm[SMA_C0 + j] = b_ih[row] + b_hh[row] + cb;
    }
    int tp = blockIdx.y, nbase = blockIdx.x * 128;
    for (int i = tid; i < 4096; i += 256) {
        int r = i >> 5, k = i & 31;
        sm[SMA_X + k * 132 + r] = Xf[((size_t)(nbase + r) * HOR + tp) * 32 + k];
    }
    __syncthreads();

    int u = tid & 63, rg = tid >> 6;
    float ci = sm[SMA_C0 + u], cg0 = sm[SMA_C0 + 64 + u], co = sm[SMA_C0 + 128 + u];

    #pragma unroll 1
    for (int rr = 0; rr < 4; rr++) {
        int r0 = rg * 32 + rr * 8;
        float ai[8], ag[8], ao[8];
        #pragma unroll
        for (int i = 0; i < 8; i++) { ai[i] = ci; ag[i] = cg0; ao[i] = co; }
        #pragma unroll 8
        for (int k = 0; k < 32; k++) {
            float wi = sm[SMA_W + k * 193 + u];
            float wg = sm[SMA_W + k * 193 + 64 + u];
            float wo = sm[SMA_W + k * 193 + 128 + u];
            float4 xa = *(const float4*)&sm[SMA_X + k * 132 + r0];
            float4 xb = *(const float4*)&sm[SMA_X + k * 132 + r0 + 4];
            GATE_FMA24(wi, wg, wo, xa, xb)
        }
        float* gi = &g_Gx[((size_t)tp * 192 + u) * 4096 + nbase + r0];
        float* gg = &g_Gx[((size_t)tp * 192 + 64 + u) * 4096 + nbase + r0];
        float* go = &g_Gx[((size_t)tp * 192 + 128 + u) * 4096 + nbase + r0];
        *(float4*)gi       = make_float4(ai[0], ai[1], ai[2], ai[3]);
        *(float4*)(gi + 4) = make_float4(ai[4], ai[5], ai[6], ai[7]);
        *(float4*)gg       = make_float4(ag[0], ag[1], ag[2], ag[3]);
        *(float4*)(gg + 4) = make_float4(ag[4], ag[5], ag[6], ag[7]);
        *(float4*)go       = make_float4(ao[0], ao[1], ao[2], ao[3]);
        *(float4*)(go + 4) = make_float4(ao[4], ao[5], ao[6], ao[7]);
    }
}

// =============================================================================
// P2: layer1 + head for teacher rows
#define SM2_W   0        // 64*193 = 12352
#define SM2_X   12352    // 64*132 = 8448
#define SM2_C1  20800    // 192
#define SM2_WMU 20992    // 64
#define SM2_WSG 21056    // 64
#define SM2_H2  21120    // 128*65 = 8320
#define SM2_FLOATS 29440
#define SM2_BYTES (SM2_FLOATS * 4)

__global__ void __launch_bounds__(256) kP2(
    const float* __restrict__ W_ih, const float* __restrict__ b_ih,
    const float* __restrict__ b_hh, const float* __restrict__ W_mu,
    const float* __restrict__ b_mu, const float* __restrict__ W_sigma,
    const float* __restrict__ b_sigma, const float* __restrict__ y,
    float* __restrict__ out_yp, float* __restrict__ out_mu,
    float* __restrict__ out_sg)
{
    extern __shared__ float sm[];
    int tid = threadIdx.x;
    for (int i = tid; i < 12288; i += 256) {
        int g = i >> 12, u = (i >> 6) & 63, k = i & 63;
        sm[SM2_W + k * 193 + g * 64 + u] = W_ih[16384 + rowsel(g, u) * 64 + k];
    }
    for (int j = tid; j < 192; j += 256) {
        int g = j >> 6, u = j & 63, row = rowsel(g, u);
        sm[SM2_C1 + j] = b_ih[256 + row] + b_hh[256 + row];
    }
    for (int i = tid; i < 64; i += 256) {
        sm[SM2_WMU + i] = W_mu[i];
        sm[SM2_WSG + i] = W_sigma[i];
    }
    int rowbase = blockIdx.x * 128;
    const float* hg = g_h1 + (size_t)rowbase * 64;
    for (int i = tid; i < 8192; i += 256)
        sm[SM2_X + (i & 63) * 132 + (i >> 6)] = hg[i];
    __syncthreads();

    int u = tid & 63, rg = tid >> 6;
    float ci = sm[SM2_C1 + u], cg0 = sm[SM2_C1 + 64 + u], co = sm[SM2_C1 + 128 + u];

    #pragma unroll 1
    for (int rr = 0; rr < 4; rr++) {
        int r0 = rg * 32 + rr * 8;
        float ai[8], ag[8], ao[8];
        #pragma unroll
        for (int i = 0; i < 8; i++) { ai[i] = ci; ag[i] = cg0; ao[i] = co; }
        #pragma unroll 8
        for (int k = 0; k < 64; k++) {
            float wi = sm[SM2_W + k * 193 + u];
            float wg = sm[SM2_W + k * 193 + 64 + u];
            float wo = sm[SM2_W + k * 193 + 128 + u];
            float4 xa = *(const float4*)&sm[SM2_X + k * 132 + r0];
            float4 xb = *(const float4*)&sm[SM2_X + k * 132 + r0 + 4];
            GATE_FMA24(wi, wg, wo, xa, xb)
        }
        #pragma unroll
        for (int i = 0; i < 8; i++) {
            float c = sigapx(ai[i]) * tanhapx(ag[i]);
            float h = sigapx(ao[i]) * tanhapx(c);
            sm[SM2_H2 + (r0 + i) * 65 + u] = fmaxf(h, 0.f);
        }
    }
    __syncthreads();

    if (tid < 128) {
        int grow = rowbase + tid;
        int n = grow / 168, t = grow - n * 168;
        float mu = b_mu[0], sg = b_sigma[0];
        #pragma unroll 16
        for (int k = 0; k < 64; k++) {
            float h = sm[SM2_H2 + tid * 65 + k];
            mu = fmaf(h, sm[SM2_WMU + k], mu);
            sg = fmaf(h, sm[SM2_WSG + k], sg);
        }
        float sigma = fsoftplus(sg) + 1e-6f;
        out_mu[n * TT + t] = mu;
        out_sg[n * TT + t] = sigma;
        if (t == SEQL - 1) {
            float yn = y[grow];
            float inv = __fdividef(1.f, sigma);
            float d = yn - mu;
            float lik = 0.3989422804014327f * inv * __expf(-0.5f * d * d * inv * inv);
            out_yp[n * HOR] = lik;
            g_carry[n] = lik;
        }
    }
}

// =============================================================================
// kB: 24-step recurrence; block = 32 series x 8 warps (8 units per warp)
#define SMB_WJ  0        // 192*64 = 12288, [j][k]
#define SMB_V   12288
#define SMB_C1  12480
#define SMB_WMU 12672
#define SMB_WSG 12736
#define SMB_H1  12800    // 32*65 = 2080
#define SMB_PMU 14880    // 8*33
#define SMB_PSG 15144    // 8*33
#define SMB_YN  15408    // 32
#define SMB_FLOATS 15440
#define SMB_BYTES (SMB_FLOATS * 4)

__global__ void __launch_bounds__(256) kB(
    const float* __restrict__ W_ih, const float* __restrict__ b_ih,
    const float* __restrict__ b_hh, const float* __restrict__ W_embed,
    const float* __restrict__ b_embed, const float* __restrict__ W_mu,
    const float* __restrict__ b_mu, const float* __restrict__ W_sigma,
    const float* __restrict__ b_sigma,
    float* __restrict__ out_yp, float* __restrict__ out_mu,
    float* __restrict__ out_sg)
{
    extern __shared__ float sm[];
    int tid = threadIdx.x;
    for (int i = tid; i < 12288; i += 256) {
        int g = i >> 12, u = (i >> 6) & 63, k = i & 63;
        sm[SMB_WJ + (g * 64 + u) * 64 + k] = W_ih[16384 + rowsel(g, u) * 64 + k];
    }
    for (int j = tid; j < 192; j += 256) {
        int g = j >> 6, u = j & 63, row = rowsel(g, u);
        float v = 0.f;
        #pragma unroll
        for (int e = 0; e < 32; e++)
            v = fmaf(W_ih[row * 64 + 32 + e], W_embed[e], v);
        sm[SMB_V + j] = v;
        sm[SMB_C1 + j] = b_ih[256 + row] + b_hh[256 + row];
    }
    for (int i = tid; i < 64; i += 256) {
        sm[SMB_WMU + i] = W_mu[i];
        sm[SMB_WSG + i] = W_sigma[i];
    }
    __syncthreads();

    int w = tid >> 5, s = tid & 31;
    int n = blockIdx.x * 32 + s, ub = w * 8;
    float yn = g_carry[n];
    float bmu = b_mu[0], bsg = b_sigma[0];

    #pragma unroll 1
    for (int t = SEQL; t < TT; t++) {
        int tp = t - SEQL;
        const float* gx = g_Gx + (size_t)tp * 192 * 4096 + n;
        #pragma unroll
        for (int j = 0; j < 8; j++) {
            int uu = ub + j;
            float ai = fmaf(yn, sm[SMB_V + uu], gx[uu * 4096]);
            float ag = fmaf(yn, sm[SMB_V + 64 + uu], gx[(64 + uu) * 4096]);
            float ao = fmaf(yn, sm[SMB_V + 128 + uu], gx[(128 + uu) * 4096]);
            float c = sigapx(ai) * tanhapx(ag);
            sm[SMB_H1 + s * 65 + uu] = sigapx(ao) * tanhapx(c);
        }
        __syncthreads();
        float h[64];
        #pragma unroll
        for (int k = 0; k < 64; k++) h[k] = sm[SMB_H1 + s * 65 + k];
        float pmu = 0.f, psg = 0.f;
        #pragma unroll 2
        for (int j = 0; j < 8; j++) {
            int uu = ub + j;
            float ai = sm[SMB_C1 + uu], ag = sm[SMB_C1 + 64 + uu], ao = sm[SMB_C1 + 128 + uu];
            const float4* wiv = (const float4*)&sm[SMB_WJ + uu * 64];
            const float4* wgv = (const float4*)&sm[SMB_WJ + (64 + uu) * 64];
            const float4* wov = (const float4*)&sm[SMB_WJ + (128 + uu) * 64];
            #pragma unroll
            for (int k4 = 0; k4 < 16; k4++) {
                float4 a = wiv[k4], b = wgv[k4], cw = wov[k4];
                float h0 = h[k4 * 4], h1v = h[k4 * 4 + 1];
                float h2v = h[k4 * 4 + 2], h3v = h[k4 * 4 + 3];
                ai = fmaf(h0, a.x, ai); ai = fmaf(h1v, a.y, ai);
                ai = fmaf(h2v, a.z, ai); ai = fmaf(h3v, a.w, ai);
                ag = fmaf(h0, b.x, ag); ag = fmaf(h1v, b.y, ag);
                ag = fmaf(h2v, b.z, ag); ag = fmaf(h3v, b.w, ag);
                ao = fmaf(h0, cw.x, ao); ao = fmaf(h1v, cw.y, ao);
                ao = fmaf(h2v, cw.z, ao); ao = fmaf(h3v, cw.w, ao);
            }
            float c = sigapx(ai) * tanhapx(ag);
            float h2 = fmaxf(sigapx(ao) * tanhapx(c), 0.f);
            pmu = fmaf(h2, sm[SMB_WMU + uu], pmu);
            psg = fmaf(h2, sm[SMB_WSG + uu], psg);
        }
        sm[SMB_PMU + w * 33 + s] = pmu;
        sm[SMB_PSG + w * 33 + s] = psg;
        __syncthreads();
        if (tid < 32) {
            float mu = bmu, sg = bsg;
            #pragma unroll
            for (int w2 = 0; w2 < 8; w2++) {
                mu += sm[SMB_PMU + w2 * 33 + s];
                sg += sm[SMB_PSG + w2 * 33 + s];
            }
            float sigma = fsoftplus(sg) + 1e-6f;
            out_mu[n * TT + t] = mu;
            out_sg[n * TT + t] = sigma;
            float inv = __fdividef(1.f, sigma);
            float d = yn - mu;
            float lik = 0.3989422804014327f * inv * __expf(-0.5f * d * d * inv * inv);
            if (t < TT - 1) out_yp[n * HOR + tp + 1] = lik;
            sm[SMB_YN + s] = lik;
        }
        __syncthreads();
        yn = sm[SMB_YN + s];
    }
}

// =============================================================================
extern "C" void kernel_launch(void* const* d_in, const int* in_sizes, int n_in,
                              void* d_out, int out_size)
{
    (void)in_sizes; (void)n_in;
    const float* X       = (const float*)d_in[0];
    const float* y       = (const float*)d_in[1];
    const float* Xf      = (const float*)d_in[2];
    const float* W_embed = (const float*)d_in[3];
    const float* b_embed = (const float*)d_in[4];
    const float* W_ih    = (const float*)d_in[5];
    const float* b_ih    = (const float*)d_in[6];
    const float* b_hh    = (const float*)d_in[7];
    const float* W_mu    = (const float*)d_in[8];
    const float* b_mu    = (const float*)d_in[9];
    const float* W_sigma = (const float*)d_in[10];
    const float* b_sigma = (const float*)d_in[11];

    float* out = (float*)d_out;
    float* yp = out;
    float* omu;
    float* osg;
    const int full = NTS * HOR + 2 * NTS * TT;
    if (out_size >= full) {
        omu = out + NTS * HOR;
        osg = omu + NTS * TT;
    } else {
        void* p0; void* p1;
        cudaGetSymbolAddress(&p0, g_mu_fb);
        cudaGetSymbolAddress(&p1, g_sg_fb);
        omu = (float*)p0; osg = (float*)p1;
    }

    cudaFuncSetAttribute(kP1a, cudaFuncAttributeMaxDynamicSharedMemorySize, SMA_BYTES);
    cudaFuncSetAttribute(kP1b, cudaFuncAttributeMaxDynamicSharedMemorySize, SMA_BYTES);
    cudaFuncSetAttribute(kP2,  cudaFuncAttributeMaxDynamicSharedMemorySize, SM2_BYTES);
    cudaFuncSetAttribute(kB,   cudaFuncAttributeMaxDynamicSharedMemorySize, SMB_BYTES);

    kP1a<<<TR / 128, 256, SMA_BYTES>>>(X, y, W_ih, b_ih, b_hh, W_embed, b_embed);
    kP1b<<<dim3(NTS / 128, HOR), 256, SMA_BYTES>>>(Xf, W_ih, b_ih, b_hh, b_embed);
    kP2<<<TR / 128, 256, SM2_BYTES>>>(W_ih, b_ih, b_hh, W_mu, b_mu, W_sigma,
                                      b_sigma, y, yp, omu, osg);
    kB<<<NTS / 32, 256, SMB_BYTES>>>(W_ih, b_ih, b_hh, W_embed, b_embed,
                                     W_mu, b_mu, W_sigma, b_sigma, yp, omu, osg);
}

// round 4
// speedup vs baseline: 2.6221x; 1.1081x over previous
#include <cuda_runtime.h>

#define NTS  4096
#define SEQL 168
#define HOR  24
#define TT   192
#define TR   (NTS*SEQL)   // 688128 teacher rows
#define FR   (NTS*HOR)    // 98304 forecast rows

typedef unsigned long long u64;

// ---- device scratch ----------------------------------------------------------
__device__ float g_h1[(size_t)TR * 64];         // [row][u]
__device__ float g_Gx[(size_t)HOR * 192 * NTS]; // [tp][j][n]
__device__ float g_carry[NTS];
__device__ float g_mu_fb[NTS * TT];
__device__ float g_sg_fb[NTS * TT];

__device__ __forceinline__ int rowsel(int g, int u) {
    // torch gate rows: i=[0,64) f=[64,128) g=[128,192) o=[192,256); f skipped
    return (g == 0) ? u : ((g == 1) ? 128 + u : 192 + u);
}
__device__ __forceinline__ float tanhapx(float x) {
    float r; asm("tanh.approx.f32 %0, %1;" : "=f"(r) : "f"(x)); return r;
}
__device__ __forceinline__ float sigapx(float x) {
    return fmaf(0.5f, tanhapx(0.5f * x), 0.5f);
}
__device__ __forceinline__ float fsoftplus(float x) {
    return (x > 15.f) ? x : __logf(1.f + __expf(x));
}

// ---- packed f32x2 helpers ----------------------------------------------------
__device__ __forceinline__ u64 pack2(float lo, float hi) {
    u64 r; asm("mov.b64 %0, {%1, %2};" : "=l"(r) : "f"(lo), "f"(hi)); return r;
}
__device__ __forceinline__ void unpack2(u64 v, float& lo, float& hi) {
    asm("mov.b64 {%0, %1}, %2;" : "=f"(lo), "=f"(hi) : "l"(v));
}
__device__ __forceinline__ u64 ffma2(u64 a, u64 b, u64 c) {
    u64 d; asm("fma.rn.f32x2 %0, %1, %2, %3;" : "=l"(d) : "l"(a), "l"(b), "l"(c));
    return d;
}

// =============================================================================
// P1a / P1b shared layout (floats)
#define SMA_W   0        // 32*193
#define SMA_X   6176     // 32*132
#define SMA_Y   10400    // 128
#define SMA_V   10528    // 192
#define SMA_C0  10720    // 192
#define SMA_FLOATS 10912
#define SMA_BYTES (SMA_FLOATS * 4)

// 12 packed FFMA2 per k-iter (was 24 FFMA)
#define GATE_FFMA2(wi2, wg2, wo2, xa, xb)                         \
    ai2[0]=ffma2(wi2, xa.x, ai2[0]); ai2[1]=ffma2(wi2, xa.y, ai2[1]); \
    ai2[2]=ffma2(wi2, xb.x, ai2[2]); ai2[3]=ffma2(wi2, xb.y, ai2[3]); \
    ag2[0]=ffma2(wg2, xa.x, ag2[0]); ag2[1]=ffma2(wg2, xa.y, ag2[1]); \
    ag2[2]=ffma2(wg2, xb.x, ag2[2]); ag2[3]=ffma2(wg2, xb.y, ag2[3]); \
    ao2[0]=ffma2(wo2, xa.x, ao2[0]); ao2[1]=ffma2(wo2, xa.y, ao2[1]); \
    ao2[2]=ffma2(wo2, xb.x, ao2[2]); ao2[3]=ffma2(wo2, xb.y, ao2[3]);

// ---- P1a: layer0 for teacher rows, writes h1 --------------------------------
__global__ void __launch_bounds__(256, 2) kP1a(
    const float* __restrict__ X, const float* __restrict__ y,
    const float* __restrict__ W_ih, const float* __restrict__ b_ih,
    const float* __restrict__ b_hh, const float* __restrict__ W_embed,
    const float* __restrict__ b_embed)
{
    extern __shared__ float sm[];
    int tid = threadIdx.x;
    for (int i = tid; i < 6144; i += 256) {
        int g = i >> 11, u = (i >> 5) & 63, k = i & 31;
        sm[SMA_W + k * 193 + g * 64 + u] = W_ih[rowsel(g, u) * 64 + k];
    }
    for (int j = tid; j < 192; j += 256) {
        int g = j >> 6, u = j & 63, row = rowsel(g, u);
        float v = 0.f, cb = 0.f;
        #pragma unroll
        for (int e = 0; e < 32; e++) {
            float w = W_ih[row * 64 + 32 + e];
            v = fmaf(w, W_embed[e], v); cb = fmaf(w, b_embed[e], cb);
        }
        sm[SMA_V + j] = v;
        sm[SMA_C0 + j] = b_ih[row] + b_hh[row] + cb;
    }
    int rowbase = blockIdx.x * 128;
    const float* xg = X + (size_t)rowbase * 32;
    for (int i = tid; i < 4096; i += 256)
        sm[SMA_X + (i & 31) * 132 + (i >> 5)] = xg[i];
    for (int i = tid; i < 128; i += 256) sm[SMA_Y + i] = y[rowbase + i];
    __syncthreads();

    int u = tid & 63, rg = tid >> 6;
    float vi = sm[SMA_V + u], vg = sm[SMA_V + 64 + u], vo = sm[SMA_V + 128 + u];
    float ci = sm[SMA_C0 + u], cg0 = sm[SMA_C0 + 64 + u], co = sm[SMA_C0 + 128 + u];

    #pragma unroll 1
    for (int rr = 0; rr < 4; rr++) {
        int r0 = rg * 32 + rr * 8;
        u64 ai2[4], ag2[4], ao2[4];
        #pragma unroll
        for (int p = 0; p < 4; p++) {
            float y0 = sm[SMA_Y + r0 + 2 * p], y1 = sm[SMA_Y + r0 + 2 * p + 1];
            ai2[p] = pack2(fmaf(y0, vi, ci),  fmaf(y1, vi, ci));
            ag2[p] = pack2(fmaf(y0, vg, cg0), fmaf(y1, vg, cg0));
            ao2[p] = pack2(fmaf(y0, vo, co),  fmaf(y1, vo, co));
        }
        #pragma unroll 8
        for (int k = 0; k < 32; k++) {
            float wi = sm[SMA_W + k * 193 + u];
            float wg = sm[SMA_W + k * 193 + 64 + u];
            float wo = sm[SMA_W + k * 193 + 128 + u];
            u64 wi2 = pack2(wi, wi), wg2 = pack2(wg, wg), wo2 = pack2(wo, wo);
            ulonglong2 xa = *(const ulonglong2*)&sm[SMA_X + k * 132 + r0];
            ulonglong2 xb = *(const ulonglong2*)&sm[SMA_X + k * 132 + r0 + 4];
            GATE_FFMA2(wi2, wg2, wo2, xa, xb)
        }
        #pragma unroll
        for (int p = 0; p < 4; p++) {
            float a0, a1, b0, b1, c0, c1;
            unpack2(ai2[p], a0, a1); unpack2(ag2[p], b0, b1); unpack2(ao2[p], c0, c1);
            float cc0 = sigapx(a0) * tanhapx(b0);
            float cc1 = sigapx(a1) * tanhapx(b1);
            g_h1[(size_t)(rowbase + r0 + 2 * p) * 64 + u]     = sigapx(c0) * tanhapx(cc0);
            g_h1[(size_t)(rowbase + r0 + 2 * p + 1) * 64 + u] = sigapx(c1) * tanhapx(cc1);
        }
    }
}

// ---- P1b: layer0 x-part for forecast rows, writes Gx ------------------------
__global__ void __launch_bounds__(256, 2) kP1b(
    const float* __restrict__ Xf,
    const float* __restrict__ W_ih, const float* __restrict__ b_ih,
    const float* __restrict__ b_hh, const float* __restrict__ b_embed)
{
    extern __shared__ float sm[];
    int tid = threadIdx.x;
    for (int i = tid; i < 6144; i += 256) {
        int g = i >> 11, u = (i >> 5) & 63, k = i & 31;
        sm[SMA_W + k * 193 + g * 64 + u] = W_ih[rowsel(g, u) * 64 + k];
    }
    for (int j = tid; j < 192; j += 256) {
        int g = j >> 6, u = j & 63, row = rowsel(g, u);
        float cb = 0.f;
        #pragma unroll
        for (int e = 0; e < 32; e++)
            cb = fmaf(W_ih[row * 64 + 32 + e], b_embed[e], cb);
        sm[SMA_C0 + j] = b_ih[row] + b_hh[row] + cb;
    }
    int tp = blockIdx.y, nbase = blockIdx.x * 128;
    for (int i = tid; i < 4096; i += 256) {
        int r = i >> 5, k = i & 31;
        sm[SMA_X + k * 132 + r] = Xf[((size_t)(nbase + r) * HOR + tp) * 32 + k];
    }
    __syncthreads();

    int u = tid & 63, rg = tid >> 6;
    float ci = sm[SMA_C0 + u], cg0 = sm[SMA_C0 + 64 + u], co = sm[SMA_C0 + 128 + u];

    #pragma unroll 1
    for (int rr = 0; rr < 4; rr++) {
        int r0 = rg * 32 + rr * 8;
        u64 ai2[4], ag2[4], ao2[4];
        #pragma unroll
        for (int p = 0; p < 4; p++) {
            ai2[p] = pack2(ci, ci);
            ag2[p] = pack2(cg0, cg0);
            ao2[p] = pack2(co, co);
        }
        #pragma unroll 8
        for (int k = 0; k < 32; k++) {
            float wi = sm[SMA_W + k * 193 + u];
            float wg = sm[SMA_W + k * 193 + 64 + u];
            float wo = sm[SMA_W + k * 193 + 128 + u];
            u64 wi2 = pack2(wi, wi), wg2 = pack2(wg, wg), wo2 = pack2(wo, wo);
            ulonglong2 xa = *(const ulonglong2*)&sm[SMA_X + k * 132 + r0];
            ulonglong2 xb = *(const ulonglong2*)&sm[SMA_X + k * 132 + r0 + 4];
            GATE_FFMA2(wi2, wg2, wo2, xa, xb)
        }
        u64* gi = (u64*)&g_Gx[((size_t)tp * 192 + u) * 4096 + nbase + r0];
        u64* gg = (u64*)&g_Gx[((size_t)tp * 192 + 64 + u) * 4096 + nbase + r0];
        u64* go = (u64*)&g_Gx[((size_t)tp * 192 + 128 + u) * 4096 + nbase + r0];
        *(ulonglong2*)gi       = make_ulonglong2(ai2[0], ai2[1]);
        *(ulonglong2*)(gi + 2) = make_ulonglong2(ai2[2], ai2[3]);
        *(ulonglong2*)gg       = make_ulonglong2(ag2[0], ag2[1]);
        *(ulonglong2*)(gg + 2) = make_ulonglong2(ag2[2], ag2[3]);
        *(ulonglong2*)go       = make_ulonglong2(ao2[0], ao2[1]);
        *(ulonglong2*)(go + 2) = make_ulonglong2(ao2[2], ao2[3]);
    }
}

// =============================================================================
// P2: layer1 + head for teacher rows
#define SM2_W   0        // 64*193 = 12352
#define SM2_X   12352    // 64*132 = 8448
#define SM2_C1  20800    // 192
#define SM2_WMU 20992    // 64
#define SM2_WSG 21056    // 64
#define SM2_H2  21120    // 128*65 = 8320
#define SM2_FLOATS 29440
#define SM2_BYTES (SM2_FLOATS * 4)

__global__ void __launch_bounds__(256) kP2(
    const float* __restrict__ W_ih, const float* __restrict__ b_ih,
    const float* __restrict__ b_hh, const float* __restrict__ W_mu,
    const float* __restrict__ b_mu, const float* __restrict__ W_sigma,
    const float* __restrict__ b_sigma, const float* __restrict__ y,
    float* __restrict__ out_yp, float* __restrict__ out_mu,
    float* __restrict__ out_sg)
{
    extern __shared__ float sm[];
    int tid = threadIdx.x;
    for (int i = tid; i < 12288; i += 256) {
        int g = i >> 12, u = (i >> 6) & 63, k = i & 63;
        sm[SM2_W + k * 193 + g * 64 + u] = W_ih[16384 + rowsel(g, u) * 64 + k];
    }
    for (int j = tid; j < 192; j += 256) {
        int g = j >> 6, u = j & 63, row = rowsel(g, u);
        sm[SM2_C1 + j] = b_ih[256 + row] + b_hh[256 + row];
    }
    for (int i = tid; i < 64; i += 256) {
        sm[SM2_WMU + i] = W_mu[i];
        sm[SM2_WSG + i] = W_sigma[i];
    }
    int rowbase = blockIdx.x * 128;
    const float* hg = g_h1 + (size_t)rowbase * 64;
    for (int i = tid; i < 8192; i += 256)
        sm[SM2_X + (i & 63) * 132 + (i >> 6)] = hg[i];
    __syncthreads();

    int u = tid & 63, rg = tid >> 6;
    float ci = sm[SM2_C1 + u], cg0 = sm[SM2_C1 + 64 + u], co = sm[SM2_C1 + 128 + u];

    #pragma unroll 1
    for (int rr = 0; rr < 4; rr++) {
        int r0 = rg * 32 + rr * 8;
        u64 ai2[4], ag2[4], ao2[4];
        #pragma unroll
        for (int p = 0; p < 4; p++) {
            ai2[p] = pack2(ci, ci);
            ag2[p] = pack2(cg0, cg0);
            ao2[p] = pack2(co, co);
        }
        #pragma unroll 8
        for (int k = 0; k < 64; k++) {
            float wi = sm[SM2_W + k * 193 + u];
            float wg = sm[SM2_W + k * 193 + 64 + u];
            float wo = sm[SM2_W + k * 193 + 128 + u];
            u64 wi2 = pack2(wi, wi), wg2 = pack2(wg, wg), wo2 = pack2(wo, wo);
            ulonglong2 xa = *(const ulonglong2*)&sm[SM2_X + k * 132 + r0];
            ulonglong2 xb = *(const ulonglong2*)&sm[SM2_X + k * 132 + r0 + 4];
            GATE_FFMA2(wi2, wg2, wo2, xa, xb)
        }
        #pragma unroll
        for (int p = 0; p < 4; p++) {
            float a0, a1, b0, b1, c0, c1;
            unpack2(ai2[p], a0, a1); unpack2(ag2[p], b0, b1); unpack2(ao2[p], c0, c1);
            float cc0 = sigapx(a0) * tanhapx(b0);
            float cc1 = sigapx(a1) * tanhapx(b1);
            sm[SM2_H2 + (r0 + 2 * p) * 65 + u]     = fmaxf(sigapx(c0) * tanhapx(cc0), 0.f);
            sm[SM2_H2 + (r0 + 2 * p + 1) * 65 + u] = fmaxf(sigapx(c1) * tanhapx(cc1), 0.f);
        }
    }
    __syncthreads();

    if (tid < 128) {
        int grow = rowbase + tid;
        int n = grow / 168, t = grow - n * 168;
        float mu = b_mu[0], sg = b_sigma[0];
        #pragma unroll 16
        for (int k = 0; k < 64; k++) {
            float h = sm[SM2_H2 + tid * 65 + k];
            mu = fmaf(h, sm[SM2_WMU + k], mu);
            sg = fmaf(h, sm[SM2_WSG + k], sg);
        }
        float sigma = fsoftplus(sg) + 1e-6f;
        out_mu[n * TT + t] = mu;
        out_sg[n * TT + t] = sigma;
        if (t == SEQL - 1) {
            float yn = y[grow];
            float inv = __fdividef(1.f, sigma);
            float d = yn - mu;
            float lik = 0.3989422804014327f * inv * __expf(-0.5f * d * d * inv * inv);
            out_yp[n * HOR] = lik;
            g_carry[n] = lik;
        }
    }
}

// =============================================================================
// kB: 24-step recurrence; block = 32 series x 8 warps (8 units per warp)
#define SMB_WJ  0        // 192*64 = 12288, [j][k]
#define SMB_V   12288
#define SMB_C1  12480
#define SMB_WMU 12672
#define SMB_WSG 12736
#define SMB_H1  12800    // 32*66 = 2112 (stride 66 for aligned u64 loads)
#define SMB_PMU 14912    // 8*33
#define SMB_PSG 15176    // 8*33
#define SMB_YN  15440    // 32
#define SMB_FLOATS 15472
#define SMB_BYTES (SMB_FLOATS * 4)

__global__ void __launch_bounds__(256) kB(
    const float* __restrict__ W_ih, const float* __restrict__ b_ih,
    const float* __restrict__ b_hh, const float* __restrict__ W_embed,
    const float* __restrict__ b_embed, const float* __restrict__ W_mu,
    const float* __restrict__ b_mu, const float* __restrict__ W_sigma,
    const float* __restrict__ b_sigma,
    float* __restrict__ out_yp, float* __restrict__ out_mu,
    float* __restrict__ out_sg)
{
    extern __shared__ float sm[];
    int tid = threadIdx.x;
    for (int i = tid; i < 12288; i += 256) {
        int g = i >> 12, u = (i >> 6) & 63, k = i & 63;
        sm[SMB_WJ + (g * 64 + u) * 64 + k] = W_ih[16384 + rowsel(g, u) * 64 + k];
    }
    for (int j = tid; j < 192; j += 256) {
        int g = j >> 6, u = j & 63, row = rowsel(g, u);
        float v = 0.f;
        #pragma unroll
        for (int e = 0; e < 32; e++)
            v = fmaf(W_ih[row * 64 + 32 + e], W_embed[e], v);
        sm[SMB_V + j] = v;
        sm[SMB_C1 + j] = b_ih[256 + row] + b_hh[256 + row];
    }
    for (int i = tid; i < 64; i += 256) {
        sm[SMB_WMU + i] = W_mu[i];
        sm[SMB_WSG + i] = W_sigma[i];
    }
    __syncthreads();

    int w = tid >> 5, s = tid & 31;
    int n = blockIdx.x * 32 + s, ub = w * 8;
    float yn = g_carry[n];
    float bmu = b_mu[0], bsg = b_sigma[0];

    #pragma unroll 1
    for (int t = SEQL; t < TT; t++) {
        int tp = t - SEQL;
        const float* gx = g_Gx + (size_t)tp * 192 * 4096 + n;
        #pragma unroll
        for (int j = 0; j < 8; j++) {
            int uu = ub + j;
            float ai = fmaf(yn, sm[SMB_V + uu], gx[uu * 4096]);
            float ag = fmaf(yn, sm[SMB_V + 64 + uu], gx[(64 + uu) * 4096]);
            float ao = fmaf(yn, sm[SMB_V + 128 + uu], gx[(128 + uu) * 4096]);
            float c = sigapx(ai) * tanhapx(ag);
            sm[SMB_H1 + s * 66 + uu] = sigapx(ao) * tanhapx(c);
        }
        __syncthreads();
        u64 hp[32];
        #pragma unroll
        for (int k2 = 0; k2 < 32; k2++)
            hp[k2] = *(const u64*)&sm[SMB_H1 + s * 66 + 2 * k2];
        float pmu = 0.f, psg = 0.f;
        #pragma unroll 2
        for (int j = 0; j < 8; j++) {
            int uu = ub + j;
            u64 ai2 = pack2(sm[SMB_C1 + uu], 0.f);
            u64 ag2 = pack2(sm[SMB_C1 + 64 + uu], 0.f);
            u64 ao2 = pack2(sm[SMB_C1 + 128 + uu], 0.f);
            const ulonglong2* wiv = (const ulonglong2*)&sm[SMB_WJ + uu * 64];
            const ulonglong2* wgv = (const ulonglong2*)&sm[SMB_WJ + (64 + uu) * 64];
            const ulonglong2* wov = (const ulonglong2*)&sm[SMB_WJ + (128 + uu) * 64];
            #pragma unroll
            for (int k4 = 0; k4 < 16; k4++) {
                ulonglong2 a = wiv[k4], b = wgv[k4], cw = wov[k4];
                u64 h0 = hp[2 * k4], h1v = hp[2 * k4 + 1];
                ai2 = ffma2(h0, a.x, ai2);  ai2 = ffma2(h1v, a.y, ai2);
                ag2 = ffma2(h0, b.x, ag2);  ag2 = ffma2(h1v, b.y, ag2);
                ao2 = ffma2(h0, cw.x, ao2); ao2 = ffma2(h1v, cw.y, ao2);
            }
            float al, ah, gl, gh, ol, oh;
            unpack2(ai2, al, ah); unpack2(ag2, gl, gh); unpack2(ao2, ol, oh);
            float ai = al + ah, ag = gl + gh, ao = ol + oh;
            float c = sigapx(ai) * tanhapx(ag);
            float h2 = fmaxf(sigapx(ao) * tanhapx(c), 0.f);
            pmu = fmaf(h2, sm[SMB_WMU + uu], pmu);
            psg = fmaf(h2, sm[SMB_WSG + uu], psg);
        }
        sm[SMB_PMU + w * 33 + s] = pmu;
        sm[SMB_PSG + w * 33 + s] = psg;
        __syncthreads();
        if (tid < 32) {
            float mu = bmu, sg = bsg;
            #pragma unroll
            for (int w2 = 0; w2 < 8; w2++) {
                mu += sm[SMB_PMU + w2 * 33 + s];
                sg += sm[SMB_PSG + w2 * 33 + s];
            }
            float sigma = fsoftplus(sg) + 1e-6f;
            out_mu[n * TT + t] = mu;
            out_sg[n * TT + t] = sigma;
            float inv = __fdividef(1.f, sigma);
            float d = yn - mu;
            float lik = 0.3989422804014327f * inv * __expf(-0.5f * d * d * inv * inv);
            if (t < TT - 1) out_yp[n * HOR + tp + 1] = lik;
            sm[SMB_YN + s] = lik;
        }
        __syncthreads();
        yn = sm[SMB_YN + s];
    }
}

// =============================================================================
extern "C" void kernel_launch(void* const* d_in, const int* in_sizes, int n_in,
                              void* d_out, int out_size)
{
    (void)in_sizes; (void)n_in;
    const float* X       = (const float*)d_in[0];
    const float* y       = (const float*)d_in[1];
    const float* Xf      = (const float*)d_in[2];
    const float* W_embed = (const float*)d_in[3];
    const float* b_embed = (const float*)d_in[4];
    const float* W_ih    = (const float*)d_in[5];
    const float* b_ih    = (const float*)d_in[6];
    const float* b_hh    = (const float*)d_in[7];
    const float* W_mu    = (const float*)d_in[8];
    const float* b_mu    = (const float*)d_in[9];
    const float* W_sigma = (const float*)d_in[10];
    const float* b_sigma = (const float*)d_in[11];

    float* out = (float*)d_out;
    float* yp = out;
    float* omu;
    float* osg;
    const int full = NTS * HOR + 2 * NTS * TT;
    if (out_size >= full) {
        omu = out + NTS * HOR;
        osg = omu + NTS * TT;
    } else {
        void* p0; void* p1;
        cudaGetSymbolAddress(&p0, g_mu_fb);
        cudaGetSymbolAddress(&p1, g_sg_fb);
        omu = (float*)p0; osg = (float*)p1;
    }

    cudaFuncSetAttribute(kP1a, cudaFuncAttributeMaxDynamicSharedMemorySize, SMA_BYTES);
    cudaFuncSetAttribute(kP1b, cudaFuncAttributeMaxDynamicSharedMemorySize, SMA_BYTES);
    cudaFuncSetAttribute(kP2,  cudaFuncAttributeMaxDynamicSharedMemorySize, SM2_BYTES);
    cudaFuncSetAttribute(kB,   cudaFuncAttributeMaxDynamicSharedMemorySize, SMB_BYTES);

    kP1a<<<TR / 128, 256, SMA_BYTES>>>(X, y, W_ih, b_ih, b_hh, W_embed, b_embed);
    kP1b<<<dim3(NTS / 128, HOR), 256, SMA_BYTES>>>(Xf, W_ih, b_ih, b_hh, b_embed);
    kP2<<<TR / 128, 256, SM2_BYTES>>>(W_ih, b_ih, b_hh, W_mu, b_mu, W_sigma,
                                      b_sigma, y, yp, omu, osg);
    kB<<<NTS / 32, 256, SMB_BYTES>>>(W_ih, b_ih, b_hh, W_embed, b_embed,
                                     W_mu, b_mu, W_sigma, b_sigma, yp, omu, osg);
}

// round 5
// speedup vs baseline: 3.0255x; 1.1539x over previous
#include <cuda_runtime.h>

#define NTS  4096
#define SEQL 168
#define HOR  24
#define TT   192
#define TR   (NTS*SEQL)   // 688128 teacher rows
#define FR   (NTS*HOR)    // 98304 forecast rows

typedef unsigned long long u64;

// ---- device scratch ----------------------------------------------------------
__device__ float g_h1[(size_t)TR * 64];         // [row][u]
__device__ float g_Gx[(size_t)HOR * 192 * NTS]; // [tp][j][n]
__device__ float g_carry[NTS];
__device__ float g_mu_fb[NTS * TT];
__device__ float g_sg_fb[NTS * TT];

__device__ __forceinline__ int rowsel(int g, int u) {
    // torch gate rows: i=[0,64) f=[64,128) g=[128,192) o=[192,256); f skipped
    return (g == 0) ? u : ((g == 1) ? 128 + u : 192 + u);
}
__device__ __forceinline__ float tanhapx(float x) {
    float r; asm("tanh.approx.f32 %0, %1;" : "=f"(r) : "f"(x)); return r;
}
__device__ __forceinline__ float sigapx(float x) {
    return fmaf(0.5f, tanhapx(0.5f * x), 0.5f);
}
__device__ __forceinline__ float fsoftplus(float x) {
    return (x > 15.f) ? x : __logf(1.f + __expf(x));
}

// ---- packed f32x2 helpers ----------------------------------------------------
__device__ __forceinline__ u64 pack2(float lo, float hi) {
    u64 r; asm("mov.b64 %0, {%1, %2};" : "=l"(r) : "f"(lo), "f"(hi)); return r;
}
__device__ __forceinline__ void unpack2(u64 v, float& lo, float& hi) {
    asm("mov.b64 {%0, %1}, %2;" : "=f"(lo), "=f"(hi) : "l"(v));
}
__device__ __forceinline__ u64 ffma2(u64 a, u64 b, u64 c) {
    u64 d; asm("fma.rn.f32x2 %0, %1, %2, %3;" : "=l"(d) : "l"(a), "l"(b), "l"(c));
    return d;
}

// =============================================================================
// P1a / P1b shared layout (floats)
#define SMA_W   0        // 32*193
#define SMA_X   6176     // 32*132
#define SMA_Y   10400    // 128
#define SMA_V   10528    // 192
#define SMA_C0  10720    // 192
#define SMA_FLOATS 10912
#define SMA_BYTES (SMA_FLOATS * 4)

// 12 packed FFMA2 per k-iter
#define GATE_FFMA2(wi2, wg2, wo2, xa, xb)                         \
    ai2[0]=ffma2(wi2, xa.x, ai2[0]); ai2[1]=ffma2(wi2, xa.y, ai2[1]); \
    ai2[2]=ffma2(wi2, xb.x, ai2[2]); ai2[3]=ffma2(wi2, xb.y, ai2[3]); \
    ag2[0]=ffma2(wg2, xa.x, ag2[0]); ag2[1]=ffma2(wg2, xa.y, ag2[1]); \
    ag2[2]=ffma2(wg2, xb.x, ag2[2]); ag2[3]=ffma2(wg2, xb.y, ag2[3]); \
    ao2[0]=ffma2(wo2, xa.x, ao2[0]); ao2[1]=ffma2(wo2, xa.y, ao2[1]); \
    ao2[2]=ffma2(wo2, xb.x, ao2[2]); ao2[3]=ffma2(wo2, xb.y, ao2[3]);

// ---- P1a: layer0 for teacher rows, writes h1 --------------------------------
__global__ void __launch_bounds__(256, 2) kP1a(
    const float* __restrict__ X, const float* __restrict__ y,
    const float* __restrict__ W_ih, const float* __restrict__ b_ih,
    const float* __restrict__ b_hh, const float* __restrict__ W_embed,
    const float* __restrict__ b_embed)
{
    extern __shared__ float sm[];
    int tid = threadIdx.x;
    for (int i = tid; i < 6144; i += 256) {
        int g = i >> 11, u = (i >> 5) & 63, k = i & 31;
        sm[SMA_W + k * 193 + g * 64 + u] = W_ih[rowsel(g, u) * 64 + k];
    }
    for (int j = tid; j < 192; j += 256) {
        int g = j >> 6, u = j & 63, row = rowsel(g, u);
        float v = 0.f, cb = 0.f;
        #pragma unroll
        for (int e = 0; e < 32; e++) {
            float w = W_ih[row * 64 + 32 + e];
            v = fmaf(w, W_embed[e], v); cb = fmaf(w, b_embed[e], cb);
        }
        sm[SMA_V + j] = v;
        sm[SMA_C0 + j] = b_ih[row] + b_hh[row] + cb;
    }
    int rowbase = blockIdx.x * 128;
    const float* xg = X + (size_t)rowbase * 32;
    for (int i = tid; i < 4096; i += 256)
        sm[SMA_X + (i & 31) * 132 + (i >> 5)] = xg[i];
    for (int i = tid; i < 128; i += 256) sm[SMA_Y + i] = y[rowbase + i];
    __syncthreads();

    int u = tid & 63, rg = tid >> 6;
    float vi = sm[SMA_V + u], vg = sm[SMA_V + 64 + u], vo = sm[SMA_V + 128 + u];
    float ci = sm[SMA_C0 + u], cg0 = sm[SMA_C0 + 64 + u], co = sm[SMA_C0 + 128 + u];

    #pragma unroll 1
    for (int rr = 0; rr < 4; rr++) {
        int r0 = rg * 32 + rr * 8;
        u64 ai2[4], ag2[4], ao2[4];
        #pragma unroll
        for (int p = 0; p < 4; p++) {
            float y0 = sm[SMA_Y + r0 + 2 * p], y1 = sm[SMA_Y + r0 + 2 * p + 1];
            ai2[p] = pack2(fmaf(y0, vi, ci),  fmaf(y1, vi, ci));
            ag2[p] = pack2(fmaf(y0, vg, cg0), fmaf(y1, vg, cg0));
            ao2[p] = pack2(fmaf(y0, vo, co),  fmaf(y1, vo, co));
        }
        #pragma unroll 8
        for (int k = 0; k < 32; k++) {
            float wi = sm[SMA_W + k * 193 + u];
            float wg = sm[SMA_W + k * 193 + 64 + u];
            float wo = sm[SMA_W + k * 193 + 128 + u];
            u64 wi2 = pack2(wi, wi), wg2 = pack2(wg, wg), wo2 = pack2(wo, wo);
            ulonglong2 xa = *(const ulonglong2*)&sm[SMA_X + k * 132 + r0];
            ulonglong2 xb = *(const ulonglong2*)&sm[SMA_X + k * 132 + r0 + 4];
            GATE_FFMA2(wi2, wg2, wo2, xa, xb)
        }
        #pragma unroll
        for (int p = 0; p < 4; p++) {
            float a0, a1, b0, b1, c0, c1;
            unpack2(ai2[p], a0, a1); unpack2(ag2[p], b0, b1); unpack2(ao2[p], c0, c1);
            float cc0 = sigapx(a0) * tanhapx(b0);
            float cc1 = sigapx(a1) * tanhapx(b1);
            g_h1[(size_t)(rowbase + r0 + 2 * p) * 64 + u]     = sigapx(c0) * tanhapx(cc0);
            g_h1[(size_t)(rowbase + r0 + 2 * p + 1) * 64 + u] = sigapx(c1) * tanhapx(cc1);
        }
    }
}

// ---- P1b: layer0 x-part for forecast rows, writes Gx ------------------------
__global__ void __launch_bounds__(256, 2) kP1b(
    const float* __restrict__ Xf,
    const float* __restrict__ W_ih, const float* __restrict__ b_ih,
    const float* __restrict__ b_hh, const float* __restrict__ b_embed)
{
    extern __shared__ float sm[];
    int tid = threadIdx.x;
    for (int i = tid; i < 6144; i += 256) {
        int g = i >> 11, u = (i >> 5) & 63, k = i & 31;
        sm[SMA_W + k * 193 + g * 64 + u] = W_ih[rowsel(g, u) * 64 + k];
    }
    for (int j = tid; j < 192; j += 256) {
        int g = j >> 6, u = j & 63, row = rowsel(g, u);
        float cb = 0.f;
        #pragma unroll
        for (int e = 0; e < 32; e++)
            cb = fmaf(W_ih[row * 64 + 32 + e], b_embed[e], cb);
        sm[SMA_C0 + j] = b_ih[row] + b_hh[row] + cb;
    }
    int tp = blockIdx.y, nbase = blockIdx.x * 128;
    for (int i = tid; i < 4096; i += 256) {
        int r = i >> 5, k = i & 31;
        sm[SMA_X + k * 132 + r] = Xf[((size_t)(nbase + r) * HOR + tp) * 32 + k];
    }
    __syncthreads();

    int u = tid & 63, rg = tid >> 6;
    float ci = sm[SMA_C0 + u], cg0 = sm[SMA_C0 + 64 + u], co = sm[SMA_C0 + 128 + u];

    #pragma unroll 1
    for (int rr = 0; rr < 4; rr++) {
        int r0 = rg * 32 + rr * 8;
        u64 ai2[4], ag2[4], ao2[4];
        #pragma unroll
        for (int p = 0; p < 4; p++) {
            ai2[p] = pack2(ci, ci);
            ag2[p] = pack2(cg0, cg0);
            ao2[p] = pack2(co, co);
        }
        #pragma unroll 8
        for (int k = 0; k < 32; k++) {
            float wi = sm[SMA_W + k * 193 + u];
            float wg = sm[SMA_W + k * 193 + 64 + u];
            float wo = sm[SMA_W + k * 193 + 128 + u];
            u64 wi2 = pack2(wi, wi), wg2 = pack2(wg, wg), wo2 = pack2(wo, wo);
            ulonglong2 xa = *(const ulonglong2*)&sm[SMA_X + k * 132 + r0];
            ulonglong2 xb = *(const ulonglong2*)&sm[SMA_X + k * 132 + r0 + 4];
            GATE_FFMA2(wi2, wg2, wo2, xa, xb)
        }
        u64* gi = (u64*)&g_Gx[((size_t)tp * 192 + u) * 4096 + nbase + r0];
        u64* gg = (u64*)&g_Gx[((size_t)tp * 192 + 64 + u) * 4096 + nbase + r0];
        u64* go = (u64*)&g_Gx[((size_t)tp * 192 + 128 + u) * 4096 + nbase + r0];
        *(ulonglong2*)gi       = make_ulonglong2(ai2[0], ai2[1]);
        *(ulonglong2*)(gi + 2) = make_ulonglong2(ai2[2], ai2[3]);
        *(ulonglong2*)gg       = make_ulonglong2(ag2[0], ag2[1]);
        *(ulonglong2*)(gg + 2) = make_ulonglong2(ag2[2], ag2[3]);
        *(ulonglong2*)go       = make_ulonglong2(ao2[0], ao2[1]);
        *(ulonglong2*)(go + 2) = make_ulonglong2(ao2[2], ao2[3]);
    }
}

// =============================================================================
// P2: layer1 + head for teacher rows; per-rr H2 staging -> 2 blocks/SM
#define SM2_W   0        // 64*193 = 12352
#define SM2_X   12352    // 64*132 = 8448
#define SM2_C1  20800    // 192
#define SM2_WMU 20992    // 64
#define SM2_WSG 21056    // 64
#define SM2_H2  21120    // 32*65 = 2080 (per-rr)
#define SM2_FLOATS 23200
#define SM2_BYTES (SM2_FLOATS * 4)

__global__ void __launch_bounds__(256, 2) kP2(
    const float* __restrict__ W_ih, const float* __restrict__ b_ih,
    const float* __restrict__ b_hh, const float* __restrict__ W_mu,
    const float* __restrict__ b_mu, const float* __restrict__ W_sigma,
    const float* __restrict__ b_sigma, const float* __restrict__ y,
    float* __restrict__ out_yp, float* __restrict__ out_mu,
    float* __restrict__ out_sg)
{
    extern __shared__ float sm[];
    int tid = threadIdx.x;
    for (int i = tid; i < 12288; i += 256) {
        int g = i >> 12, u = (i >> 6) & 63, k = i & 63;
        sm[SM2_W + k * 193 + g * 64 + u] = W_ih[16384 + rowsel(g, u) * 64 + k];
    }
    for (int j = tid; j < 192; j += 256) {
        int g = j >> 6, u = j & 63, row = rowsel(g, u);
        sm[SM2_C1 + j] = b_ih[256 + row] + b_hh[256 + row];
    }
    for (int i = tid; i < 64; i += 256) {
        sm[SM2_WMU + i] = W_mu[i];
        sm[SM2_WSG + i] = W_sigma[i];
    }
    int rowbase = blockIdx.x * 128;
    const float* hg = g_h1 + (size_t)rowbase * 64;
    for (int i = tid; i < 8192; i += 256)
        sm[SM2_X + (i & 63) * 132 + (i >> 6)] = hg[i];
    __syncthreads();

    int u = tid & 63, rg = tid >> 6;
    float ci = sm[SM2_C1 + u], cg0 = sm[SM2_C1 + 64 + u], co = sm[SM2_C1 + 128 + u];
    float bmu = b_mu[0], bsg = b_sigma[0];

    #pragma unroll 1
    for (int rr = 0; rr < 4; rr++) {
        int r0 = rg * 32 + rr * 8;
        u64 ai2[4], ag2[4], ao2[4];
        #pragma unroll
        for (int p = 0; p < 4; p++) {
            ai2[p] = pack2(ci, ci);
            ag2[p] = pack2(cg0, cg0);
            ao2[p] = pack2(co, co);
        }
        #pragma unroll 8
        for (int k = 0; k < 64; k++) {
            float wi = sm[SM2_W + k * 193 + u];
            float wg = sm[SM2_W + k * 193 + 64 + u];
            float wo = sm[SM2_W + k * 193 + 128 + u];
            u64 wi2 = pack2(wi, wi), wg2 = pack2(wg, wg), wo2 = pack2(wo, wo);
            ulonglong2 xa = *(const ulonglong2*)&sm[SM2_X + k * 132 + r0];
            ulonglong2 xb = *(const ulonglong2*)&sm[SM2_X + k * 132 + r0 + 4];
            GATE_FFMA2(wi2, wg2, wo2, xa, xb)
        }
        // sync: previous rr's head phase must be done reading H2 (no-op for rr=0)
        __syncthreads();
        #pragma unroll
        for (int p = 0; p < 4; p++) {
            float a0, a1, b0, b1, c0, c1;
            unpack2(ai2[p], a0, a1); unpack2(ag2[p], b0, b1); unpack2(ao2[p], c0, c1);
            float cc0 = sigapx(a0) * tanhapx(b0);
            float cc1 = sigapx(a1) * tanhapx(b1);
            sm[SM2_H2 + (rg * 8 + 2 * p) * 65 + u]     = fmaxf(sigapx(c0) * tanhapx(cc0), 0.f);
            sm[SM2_H2 + (rg * 8 + 2 * p + 1) * 65 + u] = fmaxf(sigapx(c1) * tanhapx(cc1), 0.f);
        }
        __syncthreads();
        if (tid < 32) {
            int row_local = (tid >> 3) * 32 + rr * 8 + (tid & 7);
            int grow = rowbase + row_local;
            int n = grow / 168, t = grow - n * 168;
            float mu = bmu, sg = bsg;
            #pragma unroll 16
            for (int k = 0; k < 64; k++) {
                float h = sm[SM2_H2 + tid * 65 + k];
                mu = fmaf(h, sm[SM2_WMU + k], mu);
                sg = fmaf(h, sm[SM2_WSG + k], sg);
            }
            float sigma = fsoftplus(sg) + 1e-6f;
            out_mu[n * TT + t] = mu;
            out_sg[n * TT + t] = sigma;
            if (t == SEQL - 1) {
                float yn = y[grow];
                float inv = __fdividef(1.f, sigma);
                float d = yn - mu;
                float lik = 0.3989422804014327f * inv * __expf(-0.5f * d * d * inv * inv);
                out_yp[n * HOR] = lik;
                g_carry[n] = lik;
            }
        }
    }
}

// =============================================================================
// kB: 24-step recurrence; block = 32 series x 16 warps (4 units per warp)
#define SMB_WJ  0        // 192*64 = 12288, [j][k]
#define SMB_V   12288
#define SMB_C1  12480
#define SMB_WMU 12672
#define SMB_WSG 12736
#define SMB_H1  12800    // 32*66 = 2112 (stride 66 for aligned u64 loads)
#define SMB_PMU 14912    // 16*33 = 528
#define SMB_PSG 15440    // 528
#define SMB_YN  15968    // 32
#define SMB_FLOATS 16000
#define SMB_BYTES (SMB_FLOATS * 4)

__global__ void __launch_bounds__(512) kB(
    const float* __restrict__ W_ih, const float* __restrict__ b_ih,
    const float* __restrict__ b_hh, const float* __restrict__ W_embed,
    const float* __restrict__ b_embed, const float* __restrict__ W_mu,
    const float* __restrict__ b_mu, const float* __restrict__ W_sigma,
    const float* __restrict__ b_sigma,
    float* __restrict__ out_yp, float* __restrict__ out_mu,
    float* __restrict__ out_sg)
{
    extern __shared__ float sm[];
    int tid = threadIdx.x;
    for (int i = tid; i < 12288; i += 512) {
        int g = i >> 12, u = (i >> 6) & 63, k = i & 63;
        sm[SMB_WJ + (g * 64 + u) * 64 + k] = W_ih[16384 + rowsel(g, u) * 64 + k];
    }
    for (int j = tid; j < 192; j += 512) {
        int g = j >> 6, u = j & 63, row = rowsel(g, u);
        float v = 0.f;
        #pragma unroll
        for (int e = 0; e < 32; e++)
            v = fmaf(W_ih[row * 64 + 32 + e], W_embed[e], v);
        sm[SMB_V + j] = v;
        sm[SMB_C1 + j] = b_ih[256 + row] + b_hh[256 + row];
    }
    for (int i = tid; i < 64; i += 512) {
        sm[SMB_WMU + i] = W_mu[i];
        sm[SMB_WSG + i] = W_sigma[i];
    }
    __syncthreads();

    int w = tid >> 5, s = tid & 31;
    int n = blockIdx.x * 32 + s, ub = w * 4;
    float yn = g_carry[n];
    float bmu = b_mu[0], bsg = b_sigma[0];

    #pragma unroll 1
    for (int t = SEQL; t < TT; t++) {
        int tp = t - SEQL;
        const float* gx = g_Gx + (size_t)tp * 192 * 4096 + n;
        #pragma unroll
        for (int j = 0; j < 4; j++) {
            int uu = ub + j;
            float ai = fmaf(yn, sm[SMB_V + uu], gx[uu * 4096]);
            float ag = fmaf(yn, sm[SMB_V + 64 + uu], gx[(64 + uu) * 4096]);
            float ao = fmaf(yn, sm[SMB_V + 128 + uu], gx[(128 + uu) * 4096]);
            float c = sigapx(ai) * tanhapx(ag);
            sm[SMB_H1 + s * 66 + uu] = sigapx(ao) * tanhapx(c);
        }
        __syncthreads();
        u64 hp[32];
        #pragma unroll
        for (int k2 = 0; k2 < 32; k2++)
            hp[k2] = *(const u64*)&sm[SMB_H1 + s * 66 + 2 * k2];
        float pmu = 0.f, psg = 0.f;
        #pragma unroll
        for (int j = 0; j < 4; j++) {
            int uu = ub + j;
            u64 ai2 = pack2(sm[SMB_C1 + uu], 0.f);
            u64 ag2 = pack2(sm[SMB_C1 + 64 + uu], 0.f);
            u64 ao2 = pack2(sm[SMB_C1 + 128 + uu], 0.f);
            const ulonglong2* wiv = (const ulonglong2*)&sm[SMB_WJ + uu * 64];
            const ulonglong2* wgv = (const ulonglong2*)&sm[SMB_WJ + (64 + uu) * 64];
            const ulonglong2* wov = (const ulonglong2*)&sm[SMB_WJ + (128 + uu) * 64];
            #pragma unroll
            for (int k4 = 0; k4 < 16; k4++) {
                ulonglong2 a = wiv[k4], b = wgv[k4], cw = wov[k4];
                u64 h0 = hp[2 * k4], h1v = hp[2 * k4 + 1];
                ai2 = ffma2(h0, a.x, ai2);  ai2 = ffma2(h1v, a.y, ai2);
                ag2 = ffma2(h0, b.x, ag2);  ag2 = ffma2(h1v, b.y, ag2);
                ao2 = ffma2(h0, cw.x, ao2); ao2 = ffma2(h1v, cw.y, ao2);
            }
            float al, ah, gl, gh, ol, oh;
            unpack2(ai2, al, ah); unpack2(ag2, gl, gh); unpack2(ao2, ol, oh);
            float ai = al + ah, ag = gl + gh, ao = ol + oh;
            float c = sigapx(ai) * tanhapx(ag);
            float h2 = fmaxf(sigapx(ao) * tanhapx(c), 0.f);
            pmu = fmaf(h2, sm[SMB_WMU + uu], pmu);
            psg = fmaf(h2, sm[SMB_WSG + uu], psg);
        }
        sm[SMB_PMU + w * 33 + s] = pmu;
        sm[SMB_PSG + w * 33 + s] = psg;
        __syncthreads();
        if (tid < 32) {
            float mu = bmu, sg = bsg;
            #pragma unroll
            for (int w2 = 0; w2 < 16; w2++) {
                mu += sm[SMB_PMU + w2 * 33 + s];
                sg += sm[SMB_PSG + w2 * 33 + s];
            }
            float sigma = fsoftplus(sg) + 1e-6f;
            out_mu[n * TT + t] = mu;
            out_sg[n * TT + t] = sigma;
            float inv = __fdividef(1.f, sigma);
            float d = yn - mu;
            float lik = 0.3989422804014327f * inv * __expf(-0.5f * d * d * inv * inv);
            if (t < TT - 1) out_yp[n * HOR + tp + 1] = lik;
            sm[SMB_YN + s] = lik;
        }
        __syncthreads();
        yn = sm[SMB_YN + s];
    }
}

// =============================================================================
extern "C" void kernel_launch(void* const* d_in, const int* in_sizes, int n_in,
                              void* d_out, int out_size)
{
    (void)in_sizes; (void)n_in;
    const float* X       = (const float*)d_in[0];
    const float* y       = (const float*)d_in[1];
    const float* Xf      = (const float*)d_in[2];
    const float* W_embed = (const float*)d_in[3];
    const float* b_embed = (const float*)d_in[4];
    const float* W_ih    = (const float*)d_in[5];
    const float* b_ih    = (const float*)d_in[6];
    const float* b_hh    = (const float*)d_in[7];
    const float* W_mu    = (const float*)d_in[8];
    const float* b_mu    = (const float*)d_in[9];
    const float* W_sigma = (const float*)d_in[10];
    const float* b_sigma = (const float*)d_in[11];

    float* out = (float*)d_out;
    float* yp = out;
    float* omu;
    float* osg;
    const int full = NTS * HOR + 2 * NTS * TT;
    if (out_size >= full) {
        omu = out + NTS * HOR;
        osg = omu + NTS * TT;
    } else {
        void* p0; void* p1;
        cudaGetSymbolAddress(&p0, g_mu_fb);
        cudaGetSymbolAddress(&p1, g_sg_fb);
        omu = (float*)p0; osg = (float*)p1;
    }

    cudaFuncSetAttribute(kP1a, cudaFuncAttributeMaxDynamicSharedMemorySize, SMA_BYTES);
    cudaFuncSetAttribute(kP1b, cudaFuncAttributeMaxDynamicSharedMemorySize, SMA_BYTES);
    cudaFuncSetAttribute(kP2,  cudaFuncAttributeMaxDynamicSharedMemorySize, SM2_BYTES);
    cudaFuncSetAttribute(kB,   cudaFuncAttributeMaxDynamicSharedMemorySize, SMB_BYTES);

    kP1a<<<TR / 128, 256, SMA_BYTES>>>(X, y, W_ih, b_ih, b_hh, W_embed, b_embed);
    kP1b<<<dim3(NTS / 128, HOR), 256, SMA_BYTES>>>(Xf, W_ih, b_ih, b_hh, b_embed);
    kP2<<<TR / 128, 256, SM2_BYTES>>>(W_ih, b_ih, b_hh, W_mu, b_mu, W_sigma,
                                      b_sigma, y, yp, omu, osg);
    kB<<<NTS / 32, 512, SMB_BYTES>>>(W_ih, b_ih, b_hh, W_embed, b_embed,
                                     W_mu, b_mu, W_sigma, b_sigma, yp, omu, osg);
}

// round 7
// speedup vs baseline: 3.0560x; 1.0101x over previous
#include <cuda_runtime.h>

#define NTS  4096
#define SEQL 168
#define HOR  24
#define TT   192
#define TR   (NTS*SEQL)   // 688128 teacher rows
#define FR   (NTS*HOR)    // 98304 forecast rows

typedef unsigned long long u64;

// ---- device scratch ----------------------------------------------------------
__device__ float g_h1[(size_t)TR * 64];         // [row][u]
__device__ float g_Gx[(size_t)HOR * 192 * NTS]; // [tp][j][n]
__device__ float g_carry[NTS];
__device__ float g_mu_fb[NTS * TT];
__device__ float g_sg_fb[NTS * TT];

__device__ __forceinline__ int rowsel(int g, int u) {
    // torch gate rows: i=[0,64) f=[64,128) g=[128,192) o=[192,256); f skipped
    return (g == 0) ? u : ((g == 1) ? 128 + u : 192 + u);
}
__device__ __forceinline__ float tanhapx(float x) {
    float r; asm("tanh.approx.f32 %0, %1;" : "=f"(r) : "f"(x)); return r;
}
__device__ __forceinline__ float sigapx(float x) {
    return fmaf(0.5f, tanhapx(0.5f * x), 0.5f);
}
__device__ __forceinline__ float fsoftplus(float x) {
    return (x > 15.f) ? x : __logf(1.f + __expf(x));
}

// ---- packed f32x2 helpers ----------------------------------------------------
__device__ __forceinline__ u64 pack2(float lo, float hi) {
    u64 r; asm("mov.b64 %0, {%1, %2};" : "=l"(r) : "f"(lo), "f"(hi)); return r;
}
__device__ __forceinline__ void unpack2(u64 v, float& lo, float& hi) {
    asm("mov.b64 {%0, %1}, %2;" : "=f"(lo), "=f"(hi) : "l"(v));
}
__device__ __forceinline__ u64 ffma2(u64 a, u64 b, u64 c) {
    u64 d; asm("fma.rn.f32x2 %0, %1, %2, %3;" : "=l"(d) : "l"(a), "l"(b), "l"(c));
    return d;
}

// =============================================================================
// P1a / P1b shared layout (floats)
#define SMA_W   0        // 32*193
#define SMA_X   6176     // 32*132
#define SMA_Y   10400    // 128
#define SMA_V   10528    // 192
#define SMA_C0  10720    // 192
#define SMA_FLOATS 10912
#define SMA_BYTES (SMA_FLOATS * 4)

// 24 packed FFMA2 per k-iter across 16 rows (xa..xd = 4x ulonglong2)
#define GATE_FFMA2_16(wi2, wg2, wo2, xa, xb, xc, xd)                      \
    ai2[0]=ffma2(wi2, xa.x, ai2[0]); ai2[1]=ffma2(wi2, xa.y, ai2[1]);     \
    ai2[2]=ffma2(wi2, xb.x, ai2[2]); ai2[3]=ffma2(wi2, xb.y, ai2[3]);     \
    ai2[4]=ffma2(wi2, xc.x, ai2[4]); ai2[5]=ffma2(wi2, xc.y, ai2[5]);     \
    ai2[6]=ffma2(wi2, xd.x, ai2[6]); ai2[7]=ffma2(wi2, xd.y, ai2[7]);     \
    ag2[0]=ffma2(wg2, xa.x, ag2[0]); ag2[1]=ffma2(wg2, xa.y, ag2[1]);     \
    ag2[2]=ffma2(wg2, xb.x, ag2[2]); ag2[3]=ffma2(wg2, xb.y, ag2[3]);     \
    ag2[4]=ffma2(wg2, xc.x, ag2[4]); ag2[5]=ffma2(wg2, xc.y, ag2[5]);     \
    ag2[6]=ffma2(wg2, xd.x, ag2[6]); ag2[7]=ffma2(wg2, xd.y, ag2[7]);     \
    ao2[0]=ffma2(wo2, xa.x, ao2[0]); ao2[1]=ffma2(wo2, xa.y, ao2[1]);     \
    ao2[2]=ffma2(wo2, xb.x, ao2[2]); ao2[3]=ffma2(wo2, xb.y, ao2[3]);     \
    ao2[4]=ffma2(wo2, xc.x, ao2[4]); ao2[5]=ffma2(wo2, xc.y, ao2[5]);     \
    ao2[6]=ffma2(wo2, xd.x, ao2[6]); ao2[7]=ffma2(wo2, xd.y, ao2[7]);

// ---- P1a: layer0 for teacher rows, writes h1 --------------------------------
__global__ void __launch_bounds__(256, 2) kP1a(
    const float* __restrict__ X, const float* __restrict__ y,
    const float* __restrict__ W_ih, const float* __restrict__ b_ih,
    const float* __restrict__ b_hh, const float* __restrict__ W_embed,
    const float* __restrict__ b_embed)
{
    extern __shared__ float sm[];
    int tid = threadIdx.x;
    for (int i = tid; i < 6144; i += 256) {
        int g = i >> 11, u = (i >> 5) & 63, k = i & 31;
        sm[SMA_W + k * 193 + g * 64 + u] = W_ih[rowsel(g, u) * 64 + k];
    }
    for (int j = tid; j < 192; j += 256) {
        int g = j >> 6, u = j & 63, row = rowsel(g, u);
        float v = 0.f, cb = 0.f;
        #pragma unroll
        for (int e = 0; e < 32; e++) {
            float w = W_ih[row * 64 + 32 + e];
            v = fmaf(w, W_embed[e], v); cb = fmaf(w, b_embed[e], cb);
        }
        sm[SMA_V + j] = v;
        sm[SMA_C0 + j] = b_ih[row] + b_hh[row] + cb;
    }
    int rowbase = blockIdx.x * 128;
    const float* xg = X + (size_t)rowbase * 32;
    for (int i = tid; i < 4096; i += 256)
        sm[SMA_X + (i & 31) * 132 + (i >> 5)] = xg[i];
    for (int i = tid; i < 128; i += 256) sm[SMA_Y + i] = y[rowbase + i];
    __syncthreads();

    int u = tid & 63, rg = tid >> 6;
    float vi = sm[SMA_V + u], vg = sm[SMA_V + 64 + u], vo = sm[SMA_V + 128 + u];
    float ci = sm[SMA_C0 + u], cg0 = sm[SMA_C0 + 64 + u], co = sm[SMA_C0 + 128 + u];

    #pragma unroll 1
    for (int rr = 0; rr < 2; rr++) {
        int r0 = rg * 32 + rr * 16;
        u64 ai2[8], ag2[8], ao2[8];
        #pragma unroll
        for (int p = 0; p < 8; p++) {
            float y0 = sm[SMA_Y + r0 + 2 * p], y1 = sm[SMA_Y + r0 + 2 * p + 1];
            ai2[p] = pack2(fmaf(y0, vi, ci),  fmaf(y1, vi, ci));
            ag2[p] = pack2(fmaf(y0, vg, cg0), fmaf(y1, vg, cg0));
            ao2[p] = pack2(fmaf(y0, vo, co),  fmaf(y1, vo, co));
        }
        #pragma unroll 4
        for (int k = 0; k < 32; k++) {
            float wi = sm[SMA_W + k * 193 + u];
            float wg = sm[SMA_W + k * 193 + 64 + u];
            float wo = sm[SMA_W + k * 193 + 128 + u];
            u64 wi2 = pack2(wi, wi), wg2 = pack2(wg, wg), wo2 = pack2(wo, wo);
            ulonglong2 xa = *(const ulonglong2*)&sm[SMA_X + k * 132 + r0];
            ulonglong2 xb = *(const ulonglong2*)&sm[SMA_X + k * 132 + r0 + 4];
            ulonglong2 xc = *(const ulonglong2*)&sm[SMA_X + k * 132 + r0 + 8];
            ulonglong2 xd = *(const ulonglong2*)&sm[SMA_X + k * 132 + r0 + 12];
            GATE_FFMA2_16(wi2, wg2, wo2, xa, xb, xc, xd)
        }
        #pragma unroll
        for (int p = 0; p < 8; p++) {
            float a0, a1, b0, b1, c0, c1;
            unpack2(ai2[p], a0, a1); unpack2(ag2[p], b0, b1); unpack2(ao2[p], c0, c1);
            float cc0 = sigapx(a0) * tanhapx(b0);
            float cc1 = sigapx(a1) * tanhapx(b1);
            g_h1[(size_t)(rowbase + r0 + 2 * p) * 64 + u]     = sigapx(c0) * tanhapx(cc0);
            g_h1[(size_t)(rowbase + r0 + 2 * p + 1) * 64 + u] = sigapx(c1) * tanhapx(cc1);
        }
    }
}

// ---- P1b: layer0 x-part for forecast rows, writes Gx ------------------------
__global__ void __launch_bounds__(256, 2) kP1b(
    const float* __restrict__ Xf,
    const float* __restrict__ W_ih, const float* __restrict__ b_ih,
    const float* __restrict__ b_hh, const float* __restrict__ b_embed)
{
    extern __shared__ float sm[];
    int tid = threadIdx.x;
    for (int i = tid; i < 6144; i += 256) {
        int g = i >> 11, u = (i >> 5) & 63, k = i & 31;
        sm[SMA_W + k * 193 + g * 64 + u] = W_ih[rowsel(g, u) * 64 + k];
    }
    for (int j = tid; j < 192; j += 256) {
        int g = j >> 6, u = j & 63, row = rowsel(g, u);
        float cb = 0.f;
        #pragma unroll
        for (int e = 0; e < 32; e++)
            cb = fmaf(W_ih[row * 64 + 32 + e], b_embed[e], cb);
        sm[SMA_C0 + j] = b_ih[row] + b_hh[row] + cb;
    }
    int tp = blockIdx.y, nbase = blockIdx.x * 128;
    for (int i = tid; i < 4096; i += 256) {
        int r = i >> 5, k = i & 31;
        sm[SMA_X + k * 132 + r] = Xf[((size_t)(nbase + r) * HOR + tp) * 32 + k];
    }
    __syncthreads();

    int u = tid & 63, rg = tid >> 6;
    float ci = sm[SMA_C0 + u], cg0 = sm[SMA_C0 + 64 + u], co = sm[SMA_C0 + 128 + u];

    #pragma unroll 1
    for (int rr = 0; rr < 2; rr++) {
        int r0 = rg * 32 + rr * 16;
        u64 ai2[8], ag2[8], ao2[8];
        #pragma unroll
        for (int p = 0; p < 8; p++) {
            ai2[p] = pack2(ci, ci);
            ag2[p] = pack2(cg0, cg0);
            ao2[p] = pack2(co, co);
        }
        #pragma unroll 4
        for (int k = 0; k < 32; k++) {
            float wi = sm[SMA_W + k * 193 + u];
            float wg = sm[SMA_W + k * 193 + 64 + u];
            float wo = sm[SMA_W + k * 193 + 128 + u];
            u64 wi2 = pack2(wi, wi), wg2 = pack2(wg, wg), wo2 = pack2(wo, wo);
            ulonglong2 xa = *(const ulonglong2*)&sm[SMA_X + k * 132 + r0];
            ulonglong2 xb = *(const ulonglong2*)&sm[SMA_X + k * 132 + r0 + 4];
            ulonglong2 xc = *(const ulonglong2*)&sm[SMA_X + k * 132 + r0 + 8];
            ulonglong2 xd = *(const ulonglong2*)&sm[SMA_X + k * 132 + r0 + 12];
            GATE_FFMA2_16(wi2, wg2, wo2, xa, xb, xc, xd)
        }
        u64* gi = (u64*)&g_Gx[((size_t)tp * 192 + u) * 4096 + nbase + r0];
        u64* gg = (u64*)&g_Gx[((size_t)tp * 192 + 64 + u) * 4096 + nbase + r0];
        u64* go = (u64*)&g_Gx[((size_t)tp * 192 + 128 + u) * 4096 + nbase + r0];
        #pragma unroll
        for (int p = 0; p < 4; p++) {
            *(ulonglong2*)(gi + 2 * p) = make_ulonglong2(ai2[2 * p], ai2[2 * p + 1]);
            *(ulonglong2*)(gg + 2 * p) = make_ulonglong2(ag2[2 * p], ag2[2 * p + 1]);
            *(ulonglong2*)(go + 2 * p) = make_ulonglong2(ao2[2 * p], ao2[2 * p + 1]);
        }
    }
}

// =============================================================================
// P2: layer1 + head for teacher rows; 16-row tiles, 2 blocks/SM
#define SM2_W   0        // 64*193 = 12352
#define SM2_X   12352    // 64*132 = 8448
#define SM2_C1  20800    // 192
#define SM2_WMU 20992    // 64
#define SM2_WSG 21056    // 64
#define SM2_H2  21120    // 64*65 = 4160 (per-rr, compact slots)
#define SM2_FLOATS 25280
#define SM2_BYTES (SM2_FLOATS * 4)

__global__ void __launch_bounds__(256, 2) kP2(
    const float* __restrict__ W_ih, const float* __restrict__ b_ih,
    const float* __restrict__ b_hh, const float* __restrict__ W_mu,
    const float* __restrict__ b_mu, const float* __restrict__ W_sigma,
    const float* __restrict__ b_sigma, const float* __restrict__ y,
    float* __restrict__ out_yp, float* __restrict__ out_mu,
    float* __restrict__ out_sg)
{
    extern __shared__ float sm[];
    int tid = threadIdx.x;
    for (int i = tid; i < 12288; i += 256) {
        int g = i >> 12, u = (i >> 6) & 63, k = i & 63;
        sm[SM2_W + k * 193 + g * 64 + u] = W_ih[16384 + rowsel(g, u) * 64 + k];
    }
    for (int j = tid; j < 192; j += 256) {
        int g = j >> 6, u = j & 63, row = rowsel(g, u);
        sm[SM2_C1 + j] = b_ih[256 + row] + b_hh[256 + row];
    }
    for (int i = tid; i < 64; i += 256) {
        sm[SM2_WMU + i] = W_mu[i];
        sm[SM2_WSG + i] = W_sigma[i];
    }
    int rowbase = blockIdx.x * 128;
    const float* hg = g_h1 + (size_t)rowbase * 64;
    for (int i = tid; i < 8192; i += 256)
        sm[SM2_X + (i & 63) * 132 + (i >> 6)] = hg[i];
    __syncthreads();

    int u = tid & 63, rg = tid >> 6;
    float ci = sm[SM2_C1 + u], cg0 = sm[SM2_C1 + 64 + u], co = sm[SM2_C1 + 128 + u];
    float bmu = b_mu[0], bsg = b_sigma[0];

    #pragma unroll 1
    for (int rr = 0; rr < 2; rr++) {
        int r0 = rg * 32 + rr * 16;
        u64 ai2[8], ag2[8], ao2[8];
        #pragma unroll
        for (int p = 0; p < 8; p++) {
            ai2[p] = pack2(ci, ci);
            ag2[p] = pack2(cg0, cg0);
            ao2[p] = pack2(co, co);
        }
        #pragma unroll 4
        for (int k = 0; k < 64; k++) {
            float wi = sm[SM2_W + k * 193 + u];
            float wg = sm[SM2_W + k * 193 + 64 + u];
            float wo = sm[SM2_W + k * 193 + 128 + u];
            u64 wi2 = pack2(wi, wi), wg2 = pack2(wg, wg), wo2 = pack2(wo, wo);
            ulonglong2 xa = *(const ulonglong2*)&sm[SM2_X + k * 132 + r0];
            ulonglong2 xb = *(const ulonglong2*)&sm[SM2_X + k * 132 + r0 + 4];
            ulonglong2 xc = *(const ulonglong2*)&sm[SM2_X + k * 132 + r0 + 8];
            ulonglong2 xd = *(const ulonglong2*)&sm[SM2_X + k * 132 + r0 + 12];
            GATE_FFMA2_16(wi2, wg2, wo2, xa, xb, xc, xd)
        }
        // previous rr's head phase must be done reading H2 (no-op for rr=0)
        __syncthreads();
        #pragma unroll
        for (int p = 0; p < 8; p++) {
            float a0, a1, b0, b1, c0, c1;
            unpack2(ai2[p], a0, a1); unpack2(ag2[p], b0, b1); unpack2(ao2[p], c0, c1);
            float cc0 = sigapx(a0) * tanhapx(b0);
            float cc1 = sigapx(a1) * tanhapx(b1);
            int slot = rg * 16 + 2 * p;   // compact 0..63
            sm[SM2_H2 + slot * 65 + u]       = fmaxf(sigapx(c0) * tanhapx(cc0), 0.f);
            sm[SM2_H2 + (slot + 1) * 65 + u] = fmaxf(sigapx(c1) * tanhapx(cc1), 0.f);
        }
        __syncthreads();
        if (tid < 64) {
            int rg2 = tid >> 4, i = tid & 15;
            int row_local = rg2 * 32 + rr * 16 + i;
            int grow = rowbase + row_local;
            int n = grow / 168, t = grow - n * 168;
            float mu = bmu, sg = bsg;
            #pragma unroll 16
            for (int k = 0; k < 64; k++) {
                float h = sm[SM2_H2 + tid * 65 + k];
                mu = fmaf(h, sm[SM2_WMU + k], mu);
                sg = fmaf(h, sm[SM2_WSG + k], sg);
            }
            float sigma = fsoftplus(sg) + 1e-6f;
            out_mu[n * TT + t] = mu;
            out_sg[n * TT + t] = sigma;
            if (t == SEQL - 1) {
                float yn = y[grow];
                float inv = __fdividef(1.f, sigma);
                float d = yn - mu;
                float lik = 0.3989422804014327f * inv * __expf(-0.5f * d * d * inv * inv);
                out_yp[n * HOR] = lik;
                g_carry[n] = lik;
            }
        }
    }
}

// =============================================================================
// kB: 24-step recurrence; block = 32 series x 16 warps (4 units per warp)
#define SMB_WJ  0        // 192*64 = 12288, [j][k]
#define SMB_V   12288
#define SMB_C1  12480
#define SMB_WMU 12672
#define SMB_WSG 12736
#define SMB_H1  12800    // 32*66 = 2112 (stride 66 for aligned u64 loads)
#define SMB_PMU 14912    // 16*33 = 528
#define SMB_PSG 15440    // 528
#define SMB_YN  15968    // 32
#define SMB_FLOATS 16000
#define SMB_BYTES (SMB_FLOATS * 4)

__global__ void __launch_bounds__(512) kB(
    const float* __restrict__ W_ih, const float* __restrict__ b_ih,
    const float* __restrict__ b_hh, const float* __restrict__ W_embed,
    const float* __restrict__ b_embed, const float* __restrict__ W_mu,
    const float* __restrict__ b_mu, const float* __restrict__ W_sigma,
    const float* __restrict__ b_sigma,
    float* __restrict__ out_yp, float* __restrict__ out_mu,
    float* __restrict__ out_sg)
{
    extern __shared__ float sm[];
    int tid = threadIdx.x;
    for (int i = tid; i < 12288; i += 512) {
        int g = i >> 12, u = (i >> 6) & 63, k = i & 63;
        sm[SMB_WJ + (g * 64 + u) * 64 + k] = W_ih[16384 + rowsel(g, u) * 64 + k];
    }
    for (int j = tid; j < 192; j += 512) {
        int g = j >> 6, u = j & 63, row = rowsel(g, u);
        float v = 0.f;
        #pragma unroll
        for (int e = 0; e < 32; e++)
            v = fmaf(W_ih[row * 64 + 32 + e], W_embed[e], v);
        sm[SMB_V + j] = v;
        sm[SMB_C1 + j] = b_ih[256 + row] + b_hh[256 + row];
    }
    for (int i = tid; i < 64; i += 512) {
        sm[SMB_WMU + i] = W_mu[i];
        sm[SMB_WSG + i] = W_sigma[i];
    }
    __syncthreads();

    int w = tid >> 5, s = tid & 31;
    int n = blockIdx.x * 32 + s, ub = w * 4;
    float yn = g_carry[n];
    float bmu = b_mu[0], bsg = b_sigma[0];

    #pragma unroll 1
    for (int t = SEQL; t < TT; t++) {
        int tp = t - SEQL;
        const float* gx = g_Gx + (size_t)tp * 192 * 4096 + n;
        #pragma unroll
        for (int j = 0; j < 4; j++) {
            int uu = ub + j;
            float ai = fmaf(yn, sm[SMB_V + uu], gx[uu * 4096]);
            float ag = fmaf(yn, sm[SMB_V + 64 + uu], gx[(64 + uu) * 4096]);
            float ao = fmaf(yn, sm[SMB_V + 128 + uu], gx[(128 + uu) * 4096]);
            float c = sigapx(ai) * tanhapx(ag);
            sm[SMB_H1 + s * 66 + uu] = sigapx(ao) * tanhapx(c);
        }
        __syncthreads();
        u64 hp[32];
        #pragma unroll
        for (int k2 = 0; k2 < 32; k2++)
            hp[k2] = *(const u64*)&sm[SMB_H1 + s * 66 + 2 * k2];
        float pmu = 0.f, psg = 0.f;
        #pragma unroll
        for (int j = 0; j < 4; j++) {
            int uu = ub + j;
            u64 ai2 = pack2(sm[SMB_C1 + uu], 0.f);
            u64 ag2 = pack2(sm[SMB_C1 + 64 + uu], 0.f);
            u64 ao2 = pack2(sm[SMB_C1 + 128 + uu], 0.f);
            const ulonglong2* wiv = (const ulonglong2*)&sm[SMB_WJ + uu * 64];
            const ulonglong2* wgv = (const ulonglong2*)&sm[SMB_WJ + (64 + uu) * 64];
            const ulonglong2* wov = (const ulonglong2*)&sm[SMB_WJ + (128 + uu) * 64];
            #pragma unroll
            for (int k4 = 0; k4 < 16; k4++) {
                ulonglong2 a = wiv[k4], b = wgv[k4], cw = wov[k4];
                u64 h0 = hp[2 * k4], h1v = hp[2 * k4 + 1];
                ai2 = ffma2(h0, a.x, ai2);  ai2 = ffma2(h1v, a.y, ai2);
                ag2 = ffma2(h0, b.x, ag2);  ag2 = ffma2(h1v, b.y, ag2);
                ao2 = ffma2(h0, cw.x, ao2); ao2 = ffma2(h1v, cw.y, ao2);
            }
            float al, ah, gl, gh, ol, oh;
            unpack2(ai2, al, ah); unpack2(ag2, gl, gh); unpack2(ao2, ol, oh);
            float ai = al + ah, ag = gl + gh, ao = ol + oh;
            float c = sigapx(ai) * tanhapx(ag);
            float h2 = fmaxf(sigapx(ao) * tanhapx(c), 0.f);
            pmu = fmaf(h2, sm[SMB_WMU + uu], pmu);
            psg = fmaf(h2, sm[SMB_WSG + uu], psg);
        }
        sm[SMB_PMU + w * 33 + s] = pmu;
        sm[SMB_PSG + w * 33 + s] = psg;
        __syncthreads();
        if (tid < 32) {
            float mu = bmu, sg = bsg;
            #pragma unroll
            for (int w2 = 0; w2 < 16; w2++) {
                mu += sm[SMB_PMU + w2 * 33 + s];
                sg += sm[SMB_PSG + w2 * 33 + s];
            }
            float sigma = fsoftplus(sg) + 1e-6f;
            out_mu[n * TT + t] = mu;
            out_sg[n * TT + t] = sigma;
            float inv = __fdividef(1.f, sigma);
            float d = yn - mu;
            float lik = 0.3989422804014327f * inv * __expf(-0.5f * d * d * inv * inv);
            if (t < TT - 1) out_yp[n * HOR + tp + 1] = lik;
            sm[SMB_YN + s] = lik;
        }
        __syncthreads();
        yn = sm[SMB_YN + s];
    }
}

// =============================================================================
extern "C" void kernel_launch(void* const* d_in, const int* in_sizes, int n_in,
                              void* d_out, int out_size)
{
    (void)in_sizes; (void)n_in;
    const float* X       = (const float*)d_in[0];
    const float* y       = (const float*)d_in[1];
    const float* Xf      = (const float*)d_in[2];
    const float* W_embed = (const float*)d_in[3];
    const float* b_embed = (const float*)d_in[4];
    const float* W_ih    = (const float*)d_in[5];
    const float* b_ih    = (const float*)d_in[6];
    const float* b_hh    = (const float*)d_in[7];
    const float* W_mu    = (const float*)d_in[8];
    const float* b_mu    = (const float*)d_in[9];
    const float* W_sigma = (const float*)d_in[10];
    const float* b_sigma = (const float*)d_in[11];

    float* out = (float*)d_out;
    float* yp = out;
    float* omu;
    float* osg;
    const int full = NTS * HOR + 2 * NTS * TT;
    if (out_size >= full) {
        omu = out + NTS * HOR;
        osg = omu + NTS * TT;
    } else {
        void* p0; void* p1;
        cudaGetSymbolAddress(&p0, g_mu_fb);
        cudaGetSymbolAddress(&p1, g_sg_fb);
        omu = (float*)p0; osg = (float*)p1;
    }

    cudaFuncSetAttribute(kP1a, cudaFuncAttributeMaxDynamicSharedMemorySize, SMA_BYTES);
    cudaFuncSetAttribute(kP1b, cudaFuncAttributeMaxDynamicSharedMemorySize, SMA_BYTES);
    cudaFuncSetAttribute(kP2,  cudaFuncAttributeMaxDynamicSharedMemorySize, SM2_BYTES);
    cudaFuncSetAttribute(kB,   cudaFuncAttributeMaxDynamicSharedMemorySize, SMB_BYTES);

    kP1a<<<TR / 128, 256, SMA_BYTES>>>(X, y, W_ih, b_ih, b_hh, W_embed, b_embed);
    kP1b<<<dim3(NTS / 128, HOR), 256, SMA_BYTES>>>(Xf, W_ih, b_ih, b_hh, b_embed);
    kP2<<<TR / 128, 256, SM2_BYTES>>>(W_ih, b_ih, b_hh, W_mu, b_mu, W_sigma,
                                      b_sigma, y, yp, omu, osg);
    kB<<<NTS / 32, 512, SMB_BYTES>>>(W_ih, b_ih, b_hh, W_embed, b_embed,
                                     W_mu, b_mu, W_sigma, b_sigma, yp, omu, osg);
}

// round 13
// speedup vs baseline: 3.0608x; 1.0016x over previous
#include <cuda_runtime.h>
#include <cuda_bf16.h>
#include <cstdint>

#define NTS  4096
#define SEQL 168
#define HOR  24
#define TT   192
#define TR   (NTS*SEQL)   // 688128 teacher rows
#define FR   (NTS*HOR)    // 98304 forecast rows

typedef unsigned long long u64;
typedef unsigned int u32;

// ---- device scratch ----------------------------------------------------------
__device__ float g_h1[(size_t)TR * 64];         // [row][u]
__device__ float g_Gx[(size_t)HOR * 192 * NTS]; // [tp][j][n]
__device__ float g_carry[NTS];
__device__ float g_mu_fb[NTS * TT];
__device__ float g_sg_fb[NTS * TT];
// pre-split planar W1 images: [j 0..191 gate-major][k 0..63] bf16
__device__ __nv_bfloat16 g_Bhi[192 * 64];
__device__ __nv_bfloat16 g_Blo[192 * 64];

__device__ __forceinline__ int rowsel(int g, int u) {
    // torch gate rows: i=[0,64) f=[64,128) g=[128,192) o=[192,256); f skipped
    return (g == 0) ? u : ((g == 1) ? 128 + u : 192 + u);
}
__device__ __forceinline__ float tanhapx(float x) {
    float r; asm("tanh.approx.f32 %0, %1;" : "=f"(r) : "f"(x)); return r;
}
__device__ __forceinline__ float sigapx(float x) {
    return fmaf(0.5f, tanhapx(0.5f * x), 0.5f);
}
__device__ __forceinline__ float fsoftplus(float x) {
    return (x > 15.f) ? x : __logf(1.f + __expf(x));
}

// ---- packed f32x2 helpers ----------------------------------------------------
__device__ __forceinline__ u64 pack2(float lo, float hi) {
    u64 r; asm("mov.b64 %0, {%1, %2};" : "=l"(r) : "f"(lo), "f"(hi)); return r;
}
__device__ __forceinline__ void unpack2(u64 v, float& lo, float& hi) {
    asm("mov.b64 {%0, %1}, %2;" : "=f"(lo), "=f"(hi) : "l"(v));
}
__device__ __forceinline__ u64 ffma2(u64 a, u64 b, u64 c) {
    u64 d; asm("fma.rn.f32x2 %0, %1, %2, %3;" : "=l"(d) : "l"(a), "l"(b), "l"(c));
    return d;
}

// ---- warp-level bf16 MMA (sm_80 base feature; legal at target sm_103) --------
__device__ __forceinline__ void mma_bf16(float d[4], u32 a0, u32 a1, u32 a2,
                                         u32 a3, u32 b0, u32 b1) {
    asm volatile(
        "mma.sync.aligned.m16n8k16.row.col.f32.bf16.bf16.f32 "
        "{%0,%1,%2,%3}, {%4,%5,%6,%7}, {%8,%9}, {%0,%1,%2,%3};"
        : "+f"(d[0]), "+f"(d[1]), "+f"(d[2]), "+f"(d[3])
        : "r"(a0), "r"(a1), "r"(a2), "r"(a3), "r"(b0), "r"(b1));
}

// =============================================================================
// P1a / P1b shared layout (floats)  [unchanged]
#define SMA_W   0
#define SMA_X   6176
#define SMA_Y   10400
#define SMA_V   10528
#define SMA_C0  10720
#define SMA_FLOATS 10912
#define SMA_BYTES (SMA_FLOATS * 4)

#define GATE_FFMA2_16(wi2, wg2, wo2, xa, xb, xc, xd)                      \
    ai2[0]=ffma2(wi2, xa.x, ai2[0]); ai2[1]=ffma2(wi2, xa.y, ai2[1]);     \
    ai2[2]=ffma2(wi2, xb.x, ai2[2]); ai2[3]=ffma2(wi2, xb.y, ai2[3]);     \
    ai2[4]=ffma2(wi2, xc.x, ai2[4]); ai2[5]=ffma2(wi2, xc.y, ai2[5]);     \
    ai2[6]=ffma2(wi2, xd.x, ai2[6]); ai2[7]=ffma2(wi2, xd.y, ai2[7]);     \
    ag2[0]=ffma2(wg2, xa.x, ag2[0]); ag2[1]=ffma2(wg2, xa.y, ag2[1]);     \
    ag2[2]=ffma2(wg2, xb.x, ag2[2]); ag2[3]=ffma2(wg2, xb.y, ag2[3]);     \
    ag2[4]=ffma2(wg2, xc.x, ag2[4]); ag2[5]=ffma2(wg2, xc.y, ag2[5]);     \
    ag2[6]=ffma2(wg2, xd.x, ag2[6]); ag2[7]=ffma2(wg2, xd.y, ag2[7]);     \
    ao2[0]=ffma2(wo2, xa.x, ao2[0]); ao2[1]=ffma2(wo2, xa.y, ao2[1]);     \
    ao2[2]=ffma2(wo2, xb.x, ao2[2]); ao2[3]=ffma2(wo2, xb.y, ao2[3]);     \
    ao2[4]=ffma2(wo2, xc.x, ao2[4]); ao2[5]=ffma2(wo2, xc.y, ao2[5]);     \
    ao2[6]=ffma2(wo2, xd.x, ao2[6]); ao2[7]=ffma2(wo2, xd.y, ao2[7]);

// ---- P1a: layer0 for teacher rows, writes h1 (unchanged) --------------------
__global__ void __launch_bounds__(256, 2) kP1a(
    const float* __restrict__ X, const float* __restrict__ y,
    const float* __restrict__ W_ih, const float* __restrict__ b_ih,
    const float* __restrict__ b_hh, const float* __restrict__ W_embed,
    const float* __restrict__ b_embed)
{
    extern __shared__ float sm[];
    int tid = threadIdx.x;
    for (int i = tid; i < 6144; i += 256) {
        int g = i >> 11, u = (i >> 5) & 63, k = i & 31;
        sm[SMA_W + k * 193 + g * 64 + u] = W_ih[rowsel(g, u) * 64 + k];
    }
    for (int j = tid; j < 192; j += 256) {
        int g = j >> 6, u = j & 63, row = rowsel(g, u);
        float v = 0.f, cb = 0.f;
        #pragma unroll
        for (int e = 0; e < 32; e++) {
            float w = W_ih[row * 64 + 32 + e];
            v = fmaf(w, W_embed[e], v); cb = fmaf(w, b_embed[e], cb);
        }
        sm[SMA_V + j] = v;
        sm[SMA_C0 + j] = b_ih[row] + b_hh[row] + cb;
    }
    int rowbase = blockIdx.x * 128;
    const float* xg = X + (size_t)rowbase * 32;
    for (int i = tid; i < 4096; i += 256)
        sm[SMA_X + (i & 31) * 132 + (i >> 5)] = xg[i];
    for (int i = tid; i < 128; i += 256) sm[SMA_Y + i] = y[rowbase + i];
    __syncthreads();

    int u = tid & 63, rg = tid >> 6;
    float vi = sm[SMA_V + u], vg = sm[SMA_V + 64 + u], vo = sm[SMA_V + 128 + u];
    float ci = sm[SMA_C0 + u], cg0 = sm[SMA_C0 + 64 + u], co = sm[SMA_C0 + 128 + u];

    #pragma unroll 1
    for (int rr = 0; rr < 2; rr++) {
        int r0 = rg * 32 + rr * 16;
        u64 ai2[8], ag2[8], ao2[8];
        #pragma unroll
        for (int p = 0; p < 8; p++) {
            float y0 = sm[SMA_Y + r0 + 2 * p], y1 = sm[SMA_Y + r0 + 2 * p + 1];
            ai2[p] = pack2(fmaf(y0, vi, ci),  fmaf(y1, vi, ci));
            ag2[p] = pack2(fmaf(y0, vg, cg0), fmaf(y1, vg, cg0));
            ao2[p] = pack2(fmaf(y0, vo, co),  fmaf(y1, vo, co));
        }
        #pragma unroll 4
        for (int k = 0; k < 32; k++) {
            float wi = sm[SMA_W + k * 193 + u];
            float wg = sm[SMA_W + k * 193 + 64 + u];
            float wo = sm[SMA_W + k * 193 + 128 + u];
            u64 wi2 = pack2(wi, wi), wg2 = pack2(wg, wg), wo2 = pack2(wo, wo);
            ulonglong2 xa = *(const ulonglong2*)&sm[SMA_X + k * 132 + r0];
            ulonglong2 xb = *(const ulonglong2*)&sm[SMA_X + k * 132 + r0 + 4];
            ulonglong2 xc = *(const ulonglong2*)&sm[SMA_X + k * 132 + r0 + 8];
            ulonglong2 xd = *(const ulonglong2*)&sm[SMA_X + k * 132 + r0 + 12];
            GATE_FFMA2_16(wi2, wg2, wo2, xa, xb, xc, xd)
        }
        #pragma unroll
        for (int p = 0; p < 8; p++) {
            float a0, a1, b0, b1, c0, c1;
            unpack2(ai2[p], a0, a1); unpack2(ag2[p], b0, b1); unpack2(ao2[p], c0, c1);
            float cc0 = sigapx(a0) * tanhapx(b0);
            float cc1 = sigapx(a1) * tanhapx(b1);
            g_h1[(size_t)(rowbase + r0 + 2 * p) * 64 + u]     = sigapx(c0) * tanhapx(cc0);
            g_h1[(size_t)(rowbase + r0 + 2 * p + 1) * 64 + u] = sigapx(c1) * tanhapx(cc1);
        }
    }
}

// ---- P1b: layer0 x-part for forecast rows, writes Gx (unchanged) ------------
__global__ void __launch_bounds__(256, 2) kP1b(
    const float* __restrict__ Xf,
    const float* __restrict__ W_ih, const float* __restrict__ b_ih,
    const float* __restrict__ b_hh, const float* __restrict__ b_embed)
{
    extern __shared__ float sm[];
    int tid = threadIdx.x;
    for (int i = tid; i < 6144; i += 256) {
        int g = i >> 11, u = (i >> 5) & 63, k = i & 31;
        sm[SMA_W + k * 193 + g * 64 + u] = W_ih[rowsel(g, u) * 64 + k];
    }
    for (int j = tid; j < 192; j += 256) {
        int g = j >> 6, u = j & 63, row = rowsel(g, u);
        float cb = 0.f;
        #pragma unroll
        for (int e = 0; e < 32; e++)
            cb = fmaf(W_ih[row * 64 + 32 + e], b_embed[e], cb);
        sm[SMA_C0 + j] = b_ih[row] + b_hh[row] + cb;
    }
    int tp = blockIdx.y, nbase = blockIdx.x * 128;
    for (int i = tid; i < 4096; i += 256) {
        int r = i >> 5, k = i & 31;
        sm[SMA_X + k * 132 + r] = Xf[((size_t)(nbase + r) * HOR + tp) * 32 + k];
    }
    __syncthreads();

    int u = tid & 63, rg = tid >> 6;
    float ci = sm[SMA_C0 + u], cg0 = sm[SMA_C0 + 64 + u], co = sm[SMA_C0 + 128 + u];

    #pragma unroll 1
    for (int rr = 0; rr < 2; rr++) {
        int r0 = rg * 32 + rr * 16;
        u64 ai2[8], ag2[8], ao2[8];
        #pragma unroll
        for (int p = 0; p < 8; p++) {
            ai2[p] = pack2(ci, ci);
            ag2[p] = pack2(cg0, cg0);
            ao2[p] = pack2(co, co);
        }
        #pragma unroll 4
        for (int k = 0; k < 32; k++) {
            float wi = sm[SMA_W + k * 193 + u];
            float wg = sm[SMA_W + k * 193 + 64 + u];
            float wo = sm[SMA_W + k * 193 + 128 + u];
            u64 wi2 = pack2(wi, wi), wg2 = pack2(wg, wg), wo2 = pack2(wo, wo);
            ulonglong2 xa = *(const ulonglong2*)&sm[SMA_X + k * 132 + r0];
            ulonglong2 xb = *(const ulonglong2*)&sm[SMA_X + k * 132 + r0 + 4];
            ulonglong2 xc = *(const ulonglong2*)&sm[SMA_X + k * 132 + r0 + 8];
            ulonglong2 xd = *(const ulonglong2*)&sm[SMA_X + k * 132 + r0 + 12];
            GATE_FFMA2_16(wi2, wg2, wo2, xa, xb, xc, xd)
        }
        u64* gi = (u64*)&g_Gx[((size_t)tp * 192 + u) * 4096 + nbase + r0];
        u64* gg = (u64*)&g_Gx[((size_t)tp * 192 + 64 + u) * 4096 + nbase + r0];
        u64* go = (u64*)&g_Gx[((size_t)tp * 192 + 128 + u) * 4096 + nbase + r0];
        #pragma unroll
        for (int p = 0; p < 4; p++) {
            *(ulonglong2*)(gi + 2 * p) = make_ulonglong2(ai2[2 * p], ai2[2 * p + 1]);
            *(ulonglong2*)(gg + 2 * p) = make_ulonglong2(ag2[2 * p], ag2[2 * p + 1]);
            *(ulonglong2*)(go + 2 * p) = make_ulonglong2(ao2[2 * p], ao2[2 * p + 1]);
        }
    }
}

// =============================================================================
// kPrepB: split W1 into bf16 hi/lo planar images [j][k] (once per launch)
__global__ void kPrepB(const float* __restrict__ W_ih)
{
    int idx = blockIdx.x * 256 + threadIdx.x;
    if (idx >= 192 * 64) return;
    int j = idx >> 6, k = idx & 63;
    int row = rowsel(j >> 6, j & 63);
    float w = W_ih[16384 + row * 64 + k];
    __nv_bfloat16 hi = __float2bfloat16(w);
    __nv_bfloat16 lo = __float2bfloat16(w - __bfloat162float(hi));
    g_Bhi[j * 64 + k] = hi;
    g_Blo[j * 64 + k] = lo;
}

// =============================================================================
// kP2tc: layer1 + head via warp-level bf16-split mma.sync.
// Block = 256 threads (8 warps), 128 rows. Warp w owns rows [w*16, w*16+16).
// smem (bytes):
#define T2_D    0                      // 128 x 197 f32  = 100864
#define T2_AHI  100864                 // 128 x 72 bf16  = 18432
#define T2_ALO  (T2_AHI + 18432)
#define T2_BHI  (T2_ALO + 18432)       // 192 x 72 bf16  = 27648
#define T2_BLO  (T2_BHI + 27648)
#define T2_C1   (T2_BLO + 27648)       // 192 f32
#define T2_WMU  (T2_C1 + 768)          // 64 f32
#define T2_WSG  (T2_WMU + 256)         // 64 f32
#define T2_BYTES (T2_WSG + 256 + 128)  // ~190 KB

__global__ void __launch_bounds__(256) kP2tc(
    const float* __restrict__ b_ih, const float* __restrict__ b_hh,
    const float* __restrict__ W_mu, const float* __restrict__ b_mu,
    const float* __restrict__ W_sigma, const float* __restrict__ b_sigma,
    const float* __restrict__ y,
    float* __restrict__ out_yp, float* __restrict__ out_mu,
    float* __restrict__ out_sg)
{
    extern __shared__ char smc[];
    float* smf = (float*)smc;
    int tid = threadIdx.x;
    int rowbase = blockIdx.x * 128;

    // stage A: g_h1 tile -> bf16 hi/lo, pad-72 rows
    const float* hg = g_h1 + (size_t)rowbase * 64;
    for (int i = tid; i < 8192; i += 256) {
        int r = i >> 6, u = i & 63;
        float v = hg[i];
        __nv_bfloat16 hi = __float2bfloat16(v);
        __nv_bfloat16 lo = __float2bfloat16(v - __bfloat162float(hi));
        *(__nv_bfloat16*)(smc + T2_AHI + (r * 72 + u) * 2) = hi;
        *(__nv_bfloat16*)(smc + T2_ALO + (r * 72 + u) * 2) = lo;
    }
    // stage B: planar [192][64] -> pad-72 rows (u32 = 2 bf16 at a time)
    {
        const u32* sh = (const u32*)g_Bhi;
        const u32* sl = (const u32*)g_Blo;
        for (int i = tid; i < 192 * 32; i += 256) {
            int j = i >> 5, kw = i & 31;
            *(u32*)(smc + T2_BHI + (j * 72 + kw * 2) * 2) = sh[i];
            *(u32*)(smc + T2_BLO + (j * 72 + kw * 2) * 2) = sl[i];
        }
    }
    // biases + head weights
    for (int j = tid; j < 192; j += 256) {
        int row = rowsel(j >> 6, j & 63);
        smf[T2_C1 / 4 + j] = b_ih[256 + row] + b_hh[256 + row];
    }
    if (tid < 64) {
        smf[T2_WMU / 4 + tid] = W_mu[tid];
        smf[T2_WSG / 4 + tid] = W_sigma[tid];
    }
    __syncthreads();

    // MMA phase
    {
        int w = tid >> 5, lane = tid & 31;
        int g = lane >> 2, tig = lane & 3;
        int r0 = w * 16;

        // hoist A fragments for all 4 k-steps (hi and lo)
        u32 Ah[4][4], Al[4][4];
        #pragma unroll
        for (int ks = 0; ks < 4; ks++) {
            int kb = ks * 16;
            int ra = r0 + g, rb = r0 + g + 8;
            Ah[ks][0] = *(const u32*)(smc + T2_AHI + (ra * 72 + kb + 2 * tig) * 2);
            Ah[ks][1] = *(const u32*)(smc + T2_AHI + (rb * 72 + kb + 2 * tig) * 2);
            Ah[ks][2] = *(const u32*)(smc + T2_AHI + (ra * 72 + kb + 8 + 2 * tig) * 2);
            Ah[ks][3] = *(const u32*)(smc + T2_AHI + (rb * 72 + kb + 8 + 2 * tig) * 2);
            Al[ks][0] = *(const u32*)(smc + T2_ALO + (ra * 72 + kb + 2 * tig) * 2);
            Al[ks][1] = *(const u32*)(smc + T2_ALO + (rb * 72 + kb + 2 * tig) * 2);
            Al[ks][2] = *(const u32*)(smc + T2_ALO + (ra * 72 + kb + 8 + 2 * tig) * 2);
            Al[ks][3] = *(const u32*)(smc + T2_ALO + (rb * 72 + kb + 8 + 2 * tig) * 2);
        }

        float* D = smf + T2_D / 4;
        #pragma unroll 1
        for (int n0 = 0; n0 < 192; n0 += 8) {
            float d[4] = {0.f, 0.f, 0.f, 0.f};
            int nb = n0 + g;
            #pragma unroll
            for (int ks = 0; ks < 4; ks++) {
                int kb = ks * 16;
                u32 bh0 = *(const u32*)(smc + T2_BHI + (nb * 72 + kb + 2 * tig) * 2);
                u32 bh1 = *(const u32*)(smc + T2_BHI + (nb * 72 + kb + 8 + 2 * tig) * 2);
                u32 bl0 = *(const u32*)(smc + T2_BLO + (nb * 72 + kb + 2 * tig) * 2);
                u32 bl1 = *(const u32*)(smc + T2_BLO + (nb * 72 + kb + 8 + 2 * tig) * 2);
                mma_bf16(d, Ah[ks][0], Ah[ks][1], Ah[ks][2], Ah[ks][3], bh0, bh1);
                mma_bf16(d, Ah[ks][0], Ah[ks][1], Ah[ks][2], Ah[ks][3], bl0, bl1);
                mma_bf16(d, Al[ks][0], Al[ks][1], Al[ks][2], Al[ks][3], bh0, bh1);
            }
            // store D tile: rows r0+g (+8), cols n0+2*tig (+1).
            // NOTE: scalar stores — row stride 197 floats is odd, so a float2
            // store at odd rows is only 4-byte aligned (caused R12's trap).
            int c0 = n0 + 2 * tig;
            D[(r0 + g) * 197 + c0]         = d[0];
            D[(r0 + g) * 197 + c0 + 1]     = d[1];
            D[(r0 + g + 8) * 197 + c0]     = d[2];
            D[(r0 + g + 8) * 197 + c0 + 1] = d[3];
        }
    }
    __syncthreads();

    // epilogue: 2 threads per row (each 32 units), shfl-pair reduce
    {
        int row = tid >> 1, half = tid & 1;
        const float* D = smf + T2_D / 4;
        const float* Dr = D + row * 197;
        float mu = 0.f, sg = 0.f;
        #pragma unroll 8
        for (int q = 0; q < 32; q++) {
            int u = half * 32 + q;
            float ai = Dr[u]       + smf[T2_C1 / 4 + u];
            float ag = Dr[64 + u]  + smf[T2_C1 / 4 + 64 + u];
            float ao = Dr[128 + u] + smf[T2_C1 / 4 + 128 + u];
            float c  = sigapx(ai) * tanhapx(ag);
            float h2 = fmaxf(sigapx(ao) * tanhapx(c), 0.f);
            mu = fmaf(h2, smf[T2_WMU / 4 + u], mu);
            sg = fmaf(h2, smf[T2_WSG / 4 + u], sg);
        }
        mu += __shfl_xor_sync(0xffffffffu, mu, 1);
        sg += __shfl_xor_sync(0xffffffffu, sg, 1);
        if (half == 0) {
            mu += b_mu[0];
            sg += b_sigma[0];
            int grow = rowbase + row;
            int n = grow / SEQL, t = grow - n * SEQL;
            float sigma = fsoftplus(sg) + 1e-6f;
            out_mu[n * TT + t] = mu;
            out_sg[n * TT + t] = sigma;
            if (t == SEQL - 1) {
                float yn = y[grow];
                float inv = __fdividef(1.f, sigma);
                float dd = yn - mu;
                float lik = 0.3989422804014327f * inv * __expf(-0.5f * dd * dd * inv * inv);
                out_yp[n * HOR] = lik;
                g_carry[n] = lik;
            }
        }
    }
}

// =============================================================================
// kB: 24-step recurrence (unchanged)
#define SMB_WJ  0
#define SMB_V   12288
#define SMB_C1  12480
#define SMB_WMU 12672
#define SMB_WSG 12736
#define SMB_H1  12800
#define SMB_PMU 14912
#define SMB_PSG 15440
#define SMB_YN  15968
#define SMB_FLOATS 16000
#define SMB_BYTES (SMB_FLOATS * 4)

__global__ void __launch_bounds__(512) kB(
    const float* __restrict__ W_ih, const float* __restrict__ b_ih,
    const float* __restrict__ b_hh, const float* __restrict__ W_embed,
    const float* __restrict__ b_embed, const float* __restrict__ W_mu,
    const float* __restrict__ b_mu, const float* __restrict__ W_sigma,
    const float* __restrict__ b_sigma,
    float* __restrict__ out_yp, float* __restrict__ out_mu,
    float* __restrict__ out_sg)
{
    extern __shared__ float sm[];
    int tid = threadIdx.x;
    for (int i = tid; i < 12288; i += 512) {
        int g = i >> 12, u = (i >> 6) & 63, k = i & 63;
        sm[SMB_WJ + (g * 64 + u) * 64 + k] = W_ih[16384 + rowsel(g, u) * 64 + k];
    }
    for (int j = tid; j < 192; j += 512) {
        int g = j >> 6, u = j & 63, row = rowsel(g, u);
        float v = 0.f;
        #pragma unroll
        for (int e = 0; e < 32; e++)
            v = fmaf(W_ih[row * 64 + 32 + e], W_embed[e], v);
        sm[SMB_V + j] = v;
        sm[SMB_C1 + j] = b_ih[256 + row] + b_hh[256 + row];
    }
    for (int i = tid; i < 64; i += 512) {
        sm[SMB_WMU + i] = W_mu[i];
        sm[SMB_WSG + i] = W_sigma[i];
    }
    __syncthreads();

    int w = tid >> 5, s = tid & 31;
    int n = blockIdx.x * 32 + s, ub = w * 4;
    float yn = g_carry[n];
    float bmu = b_mu[0], bsg = b_sigma[0];

    #pragma unroll 1
    for (int t = SEQL; t < TT; t++) {
        int tp = t - SEQL;
        const float* gx = g_Gx + (size_t)tp * 192 * 4096 + n;
        #pragma unroll
        for (int j = 0; j < 4; j++) {
            int uu = ub + j;
            float ai = fmaf(yn, sm[SMB_V + uu], gx[uu * 4096]);
            float ag = fmaf(yn, sm[SMB_V + 64 + uu], gx[(64 + uu) * 4096]);
            float ao = fmaf(yn, sm[SMB_V + 128 + uu], gx[(128 + uu) * 4096]);
            float c = sigapx(ai) * tanhapx(ag);
            sm[SMB_H1 + s * 66 + uu] = sigapx(ao) * tanhapx(c);
        }
        __syncthreads();
        u64 hp[32];
        #pragma unroll
        for (int k2 = 0; k2 < 32; k2++)
            hp[k2] = *(const u64*)&sm[SMB_H1 + s * 66 + 2 * k2];
        float pmu = 0.f, psg = 0.f;
        #pragma unroll
        for (int j = 0; j < 4; j++) {
            int uu = ub + j;
            u64 ai2 = pack2(sm[SMB_C1 + uu], 0.f);
            u64 ag2 = pack2(sm[SMB_C1 + 64 + uu], 0.f);
            u64 ao2 = pack2(sm[SMB_C1 + 128 + uu], 0.f);
            const ulonglong2* wiv = (const ulonglong2*)&sm[SMB_WJ + uu * 64];
            const ulonglong2* wgv = (const ulonglong2*)&sm[SMB_WJ + (64 + uu) * 64];
            const ulonglong2* wov = (const ulonglong2*)&sm[SMB_WJ + (128 + uu) * 64];
            #pragma unroll
            for (int k4 = 0; k4 < 16; k4++) {
                ulonglong2 a = wiv[k4], b = wgv[k4], cw = wov[k4];
                u64 h0 = hp[2 * k4], h1v = hp[2 * k4 + 1];
                ai2 = ffma2(h0, a.x, ai2);  ai2 = ffma2(h1v, a.y, ai2);
                ag2 = ffma2(h0, b.x, ag2);  ag2 = ffma2(h1v, b.y, ag2);
                ao2 = ffma2(h0, cw.x, ao2); ao2 = ffma2(h1v, cw.y, ao2);
            }
            float al, ah, gl, gh, ol, oh;
            unpack2(ai2, al, ah); unpack2(ag2, gl, gh); unpack2(ao2, ol, oh);
            float ai = al + ah, ag = gl + gh, ao = ol + oh;
            float c = sigapx(ai) * tanhapx(ag);
            float h2 = fmaxf(sigapx(ao) * tanhapx(c), 0.f);
            pmu = fmaf(h2, sm[SMB_WMU + uu], pmu);
            psg = fmaf(h2, sm[SMB_WSG + uu], psg);
        }
        sm[SMB_PMU + w * 33 + s] = pmu;
        sm[SMB_PSG + w * 33 + s] = psg;
        __syncthreads();
        if (tid < 32) {
            float mu = bmu, sg = bsg;
            #pragma unroll
            for (int w2 = 0; w2 < 16; w2++) {
                mu += sm[SMB_PMU + w2 * 33 + s];
                sg += sm[SMB_PSG + w2 * 33 + s];
            }
            float sigma = fsoftplus(sg) + 1e-6f;
            out_mu[n * TT + t] = mu;
            out_sg[n * TT + t] = sigma;
            float inv = __fdividef(1.f, sigma);
            float d = yn - mu;
            float lik = 0.3989422804014327f * inv * __expf(-0.5f * d * d * inv * inv);
            if (t < TT - 1) out_yp[n * HOR + tp + 1] = lik;
            sm[SMB_YN + s] = lik;
        }
        __syncthreads();
        yn = sm[SMB_YN + s];
    }
}

// =============================================================================
extern "C" void kernel_launch(void* const* d_in, const int* in_sizes, int n_in,
                              void* d_out, int out_size)
{
    (void)in_sizes; (void)n_in;
    const float* X       = (const float*)d_in[0];
    const float* y       = (const float*)d_in[1];
    const float* Xf      = (const float*)d_in[2];
    const float* W_embed = (const float*)d_in[3];
    const float* b_embed = (const float*)d_in[4];
    const float* W_ih    = (const float*)d_in[5];
    const float* b_ih    = (const float*)d_in[6];
    const float* b_hh    = (const float*)d_in[7];
    const float* W_mu    = (const float*)d_in[8];
    const float* b_mu    = (const float*)d_in[9];
    const float* W_sigma = (const float*)d_in[10];
    const float* b_sigma = (const float*)d_in[11];

    float* out = (float*)d_out;
    float* yp = out;
    float* omu;
    float* osg;
    const int full = NTS * HOR + 2 * NTS * TT;
    if (out_size >= full) {
        omu = out + NTS * HOR;
        osg = omu + NTS * TT;
    } else {
        void* p0; void* p1;
        cudaGetSymbolAddress(&p0, g_mu_fb);
        cudaGetSymbolAddress(&p1, g_sg_fb);
        omu = (float*)p0; osg = (float*)p1;
    }

    cudaFuncSetAttribute(kP1a,  cudaFuncAttributeMaxDynamicSharedMemorySize, SMA_BYTES);
    cudaFuncSetAttribute(kP1b,  cudaFuncAttributeMaxDynamicSharedMemorySize, SMA_BYTES);
    cudaFuncSetAttribute(kP2tc, cudaFuncAttributeMaxDynamicSharedMemorySize, T2_BYTES);
    cudaFuncSetAttribute(kB,    cudaFuncAttributeMaxDynamicSharedMemorySize, SMB_BYTES);

    kPrepB<<<(192 * 64 + 255) / 256, 256>>>(W_ih);
    kP1a<<<TR / 128, 256, SMA_BYTES>>>(X, y, W_ih, b_ih, b_hh, W_embed, b_embed);
    kP1b<<<dim3(NTS / 128, HOR), 256, SMA_BYTES>>>(Xf, W_ih, b_ih, b_hh, b_embed);
    kP2tc<<<TR / 128, 256, T2_BYTES>>>(b_ih, b_hh, W_mu, b_mu, W_sigma,
                                       b_sigma, y, yp, omu, osg);
    kB<<<NTS / 32, 512, SMB_BYTES>>>(W_ih, b_ih, b_hh, W_embed, b_embed,
                                     W_mu, b_mu, W_sigma, b_sigma, yp, omu, osg);
}